// round 2
// baseline (speedup 1.0000x reference)
#include <cuda_runtime.h>
#include <cuda_bf16.h>

// ---------------------------------------------------------------------------
// Persistent-kernel 2-layer LSTM (H=256, B=512, T=512, D_IN=1) + final FC.
//
// 3 graph nodes: init (zero states + transpose x), one persistent kernel that
// runs all 512 timesteps of both layers with software grid barriers, and FC.
//
// 128 CTAs x 128 threads, 1 CTA/SM (208KB smem each -> guaranteed co-resident
// on 148-SM GB300, so the spin barrier cannot deadlock).
//
// Per-CTA tile: 16 h-elems x 64 batch. All three weight slices (Whh0, Whh1,
// Wih1; 64KB each) live in SMEM for the whole run, layout [k][el][gate] so the
// 4 gate weights are one conflict-free LDS.128. h ping-pongs in global (L2).
// c states live in registers. Math: packed fma.rn.f32x2 (FFMA2).
// ---------------------------------------------------------------------------

#define Hs   256
#define Bs   512
#define Ts   512
#define HB   (Hs*Bs)

#define EL   16      // h-elems per CTA
#define BT   64      // batch per CTA
#define KC   64      // k-chunk for h staging
#define NT   128     // threads per CTA
#define NCTA 128

#define WSLICE (4*EL*Hs)          // 16384 floats = 64KB per weight slice
#define SMEM_FLOATS (3*WSLICE + KC*BT)
#define SMEM_BYTES  (SMEM_FLOATS*4)   // 212992 B = 208KB

// ---- persistent device scratch --------------------------------------------
__device__ float g_h1s[2*HB];
__device__ float g_h2s[2*HB];
__device__ float g_xT[Ts*Bs];         // x transposed to [T][B]
__device__ unsigned g_arrive = 0;
__device__ unsigned g_gen    = 0;

// ---- helpers ---------------------------------------------------------------
typedef unsigned long long u64;

__device__ __forceinline__ u64 pack2(float a, float b) {
    u64 r; asm("mov.b64 %0, {%1,%2};" : "=l"(r) : "f"(a), "f"(b)); return r;
}
__device__ __forceinline__ void fma2(u64& d, u64 a, u64 b) {
    asm("fma.rn.f32x2 %0, %1, %2, %3;" : "=l"(d) : "l"(a), "l"(b), "l"(d));
}
__device__ __forceinline__ float2 unpack2(u64 v) {
    float2 r; asm("mov.b64 {%0,%1}, %2;" : "=f"(r.x), "=f"(r.y) : "l"(v)); return r;
}
__device__ __forceinline__ float tanh_ap(float x) {
    float y; asm("tanh.approx.f32 %0, %1;" : "=f"(y) : "f"(x)); return y;
}
__device__ __forceinline__ float sig_ap(float x) {
    return fmaf(tanh_ap(0.5f * x), 0.5f, 0.5f);
}

// ---- software grid barrier (sense via monotonically increasing generation) -
__device__ __forceinline__ void grid_barrier() {
    __syncthreads();
    if (threadIdx.x == 0) {
        __threadfence();
        unsigned my = atomicAdd(&g_gen, 0u);            // read gen BEFORE arriving
        if (atomicAdd(&g_arrive, 1u) == NCTA - 1) {
            atomicExch(&g_arrive, 0u);
            __threadfence();
            atomicAdd(&g_gen, 1u);                      // release
        } else {
            while (atomicAdd(&g_gen, 0u) == my) { __nanosleep(32); }
        }
        __threadfence();
    }
    __syncthreads();
}

// ---------------------------------------------------------------------------
// One K=256 GEMM segment: acc[g][p] += W_slice(e0 rows) @ src[256][Bs] tile.
// Wsm layout: [k][el][gate] (k*64 + el*4 + g). Hsh: [KC][BT].
// Register-prefetch pipeline over 4 chunks of KC=64.
// ---------------------------------------------------------------------------
__device__ __forceinline__ void gemm_seg(
    const float* __restrict__ Wsm, const float* __restrict__ src,
    u64 acc[4][4], float* __restrict__ Hsh,
    int tid, int e, int bg, int b0)
{
    float4 pf[8];
    // prefetch chunk 0: q = j*NT + tid over KC*BT/4 float4s; row k=q>>4, col=q&15
    #pragma unroll
    for (int j = 0; j < 8; ++j) {
        int q = j * NT + tid;
        int k = q >> 4, c = q & 15;
        pf[j] = *(const float4*)&src[(size_t)k * Bs + b0 + c * 4];
    }

    for (int kc = 0; kc < Hs / KC; ++kc) {
        __syncthreads();                    // previous chunk's compute done
        #pragma unroll
        for (int j = 0; j < 8; ++j) {
            int q = j * NT + tid;
            int k = q >> 4, c = q & 15;
            *(float4*)&Hsh[k * BT + c * 4] = pf[j];
        }
        __syncthreads();
        if (kc < Hs / KC - 1) {
            #pragma unroll
            for (int j = 0; j < 8; ++j) {
                int q = j * NT + tid;
                int k = q >> 4, c = q & 15;
                pf[j] = *(const float4*)&src[(size_t)((kc + 1) * KC + k) * Bs + b0 + c * 4];
            }
        }
        const float* Wk = Wsm + (kc * KC) * (4 * EL);
        #pragma unroll 8
        for (int k = 0; k < KC; ++k) {
            float4 wv  = *(const float4*)&Wk[(k << 6) + (e << 2)];   // gates i,f,g,o
            float4 hv0 = *(const float4*)&Hsh[k * BT + (bg << 3)];
            float4 hv1 = *(const float4*)&Hsh[k * BT + (bg << 3) + 4];
            u64 h01 = pack2(hv0.x, hv0.y), h23 = pack2(hv0.z, hv0.w);
            u64 h45 = pack2(hv1.x, hv1.y), h67 = pack2(hv1.z, hv1.w);
            u64 w0 = pack2(wv.x, wv.x), w1 = pack2(wv.y, wv.y);
            u64 w2 = pack2(wv.z, wv.z), w3 = pack2(wv.w, wv.w);
            fma2(acc[0][0], w0, h01); fma2(acc[0][1], w0, h23);
            fma2(acc[0][2], w0, h45); fma2(acc[0][3], w0, h67);
            fma2(acc[1][0], w1, h01); fma2(acc[1][1], w1, h23);
            fma2(acc[1][2], w1, h45); fma2(acc[1][3], w1, h67);
            fma2(acc[2][0], w2, h01); fma2(acc[2][1], w2, h23);
            fma2(acc[2][2], w2, h45); fma2(acc[2][3], w2, h67);
            fma2(acc[3][0], w3, h01); fma2(acc[3][1], w3, h23);
            fma2(acc[3][2], w3, h45); fma2(acc[3][3], w3, h67);
        }
    }
}

__device__ __forceinline__ void zero_acc(u64 acc[4][4]) {
    #pragma unroll
    for (int g = 0; g < 4; ++g)
        #pragma unroll
        for (int p = 0; p < 4; ++p) acc[g][p] = 0ull;
}

__device__ __forceinline__ void unpack_gates(u64 acc[4][4], float gate[4][8]) {
    #pragma unroll
    for (int g = 0; g < 4; ++g)
        #pragma unroll
        for (int p = 0; p < 4; ++p) {
            float2 v = unpack2(acc[g][p]);
            gate[g][2 * p]     = v.x;
            gate[g][2 * p + 1] = v.y;
        }
}

// load weight slice from global [4H x H] into smem [k][el][g]
__device__ __forceinline__ void load_wslice(
    float* __restrict__ Wsm, const float* __restrict__ Wg, int e0, int tid)
{
    for (int q = tid; q < WSLICE / 4; q += NT) {
        int re = q >> 6;                  // 0..63 = g*16+el
        int k4 = q & 63;
        int g  = re >> 4, el = re & 15;
        float4 v = *(const float4*)&Wg[(size_t)(g * Hs + e0 + el) * Hs + k4 * 4];
        Wsm[(k4 * 4 + 0) * 64 + el * 4 + g] = v.x;
        Wsm[(k4 * 4 + 1) * 64 + el * 4 + g] = v.y;
        Wsm[(k4 * 4 + 2) * 64 + el * 4 + g] = v.z;
        Wsm[(k4 * 4 + 3) * 64 + el * 4 + g] = v.w;
    }
}

// ---------------------------------------------------------------------------
__global__ void __launch_bounds__(NT, 1) lstm_main(
    const float* __restrict__ Wih0, const float* __restrict__ Whh0,
    const float* __restrict__ bih0, const float* __restrict__ bhh0,
    const float* __restrict__ Wih1, const float* __restrict__ Whh1,
    const float* __restrict__ bih1, const float* __restrict__ bhh1)
{
    extern __shared__ float sm[];
    float* W0  = sm;                 // Whh0 slice, [k][el][g]
    float* W1h = sm + WSLICE;        // Whh1 slice
    float* W1x = sm + 2 * WSLICE;    // Wih1 slice
    float* Hsh = sm + 3 * WSLICE;    // [KC][BT]

    const int tid = threadIdx.x;
    const int e   = tid >> 3;        // 0..15
    const int bg  = tid & 7;         // 0..7 (8 batches each)
    const int e0  = (blockIdx.x & 15) * EL;
    const int b0  = (blockIdx.x >> 4) * BT;
    const int eg  = e0 + e;
    const int bb  = b0 + bg * 8;

    load_wslice(W0,  Whh0, e0, tid);
    load_wslice(W1h, Whh1, e0, tid);
    load_wslice(W1x, Wih1, e0, tid);

    // per-thread constants
    float wih0v[4], bias1[4], bias2[4];
    #pragma unroll
    for (int g = 0; g < 4; ++g) {
        int row = g * Hs + eg;
        wih0v[g] = Wih0[row];
        bias1[g] = bih0[row] + bhh0[row];
        bias2[g] = bih1[row] + bhh1[row];
    }
    float c1r[8], c2r[8];
    #pragma unroll
    for (int j = 0; j < 8; ++j) { c1r[j] = 0.0f; c2r[j] = 0.0f; }

    u64 acc[4][4];
    float gate[4][8];

    for (int i = 0; i <= Ts; ++i) {
        // ---------------- layer 1, t = i ----------------
        if (i < Ts) {
            const float* hs = g_h1s + (size_t)(i & 1) * HB;
            float*       hd = g_h1s + (size_t)((i + 1) & 1) * HB;
            zero_acc(acc);
            gemm_seg(W0, hs, acc, Hsh, tid, e, bg, b0);
            unpack_gates(acc, gate);

            float4 xv0 = *(const float4*)&g_xT[(size_t)i * Bs + bb];
            float4 xv1 = *(const float4*)&g_xT[(size_t)i * Bs + bb + 4];
            float xs[8] = {xv0.x, xv0.y, xv0.z, xv0.w, xv1.x, xv1.y, xv1.z, xv1.w};

            float hv[8];
            #pragma unroll
            for (int j = 0; j < 8; ++j) {
                float gi = fmaf(xs[j], wih0v[0], gate[0][j] + bias1[0]);
                float gf = fmaf(xs[j], wih0v[1], gate[1][j] + bias1[1]);
                float gg = fmaf(xs[j], wih0v[2], gate[2][j] + bias1[2]);
                float go = fmaf(xs[j], wih0v[3], gate[3][j] + bias1[3]);
                float iv = sig_ap(gi), fv = sig_ap(gf);
                float gv = tanh_ap(gg), ov = sig_ap(go);
                float c = fv * c1r[j] + iv * gv;
                c1r[j] = c;
                hv[j] = ov * tanh_ap(c);
            }
            *(float4*)&hd[(size_t)eg * Bs + bb]     = make_float4(hv[0], hv[1], hv[2], hv[3]);
            *(float4*)&hd[(size_t)eg * Bs + bb + 4] = make_float4(hv[4], hv[5], hv[6], hv[7]);
        }

        // ---------------- layer 2, t = i-1 --------------
        if (i >= 1) {
            const float* h2s  = g_h2s + (size_t)((i - 1) & 1) * HB;
            float*       h2d  = g_h2s + (size_t)(i & 1) * HB;
            const float* h1in = g_h1s + (size_t)(i & 1) * HB;   // h1(t=i-1)
            zero_acc(acc);
            gemm_seg(W1h, h2s,  acc, Hsh, tid, e, bg, b0);
            gemm_seg(W1x, h1in, acc, Hsh, tid, e, bg, b0);
            unpack_gates(acc, gate);

            float hv[8];
            #pragma unroll
            for (int j = 0; j < 8; ++j) {
                float gi = gate[0][j] + bias2[0];
                float gf = gate[1][j] + bias2[1];
                float gg = gate[2][j] + bias2[2];
                float go = gate[3][j] + bias2[3];
                float iv = sig_ap(gi), fv = sig_ap(gf);
                float gv = tanh_ap(gg), ov = sig_ap(go);
                float c = fv * c2r[j] + iv * gv;
                c2r[j] = c;
                hv[j] = ov * tanh_ap(c);
            }
            *(float4*)&h2d[(size_t)eg * Bs + bb]     = make_float4(hv[0], hv[1], hv[2], hv[3]);
            *(float4*)&h2d[(size_t)eg * Bs + bb + 4] = make_float4(hv[4], hv[5], hv[6], hv[7]);
        }

        grid_barrier();
    }
}

// ---------------------------------------------------------------------------
__global__ void init_states(const float* __restrict__ x) {
    int i0 = blockIdx.x * blockDim.x + threadIdx.x;
    int stride = gridDim.x * blockDim.x;
    for (int i = i0; i < 2 * HB; i += stride) g_h1s[i] = 0.0f;
    for (int i = i0; i < 2 * HB; i += stride) g_h2s[i] = 0.0f;
    for (int i = i0; i < Ts * Bs; i += stride) {
        int t = i / Bs, b = i % Bs;
        g_xT[i] = x[(size_t)b * Ts + t];
    }
}

__global__ void fc_kernel(const float* __restrict__ Wfc,
                          const float* __restrict__ bfc,
                          float* __restrict__ out)
{
    int b = blockIdx.x * blockDim.x + threadIdx.x;     // 0..511
    const float* h = g_h2s;   // final h2 is in buffer 0 (i=512 writes parity 0)
    float a0 = 0.f, a1 = 0.f, a2 = 0.f, a3 = 0.f;
    #pragma unroll 4
    for (int e = 0; e < Hs; e += 4) {
        a0 += h[(e + 0) * Bs + b] * Wfc[e + 0];
        a1 += h[(e + 1) * Bs + b] * Wfc[e + 1];
        a2 += h[(e + 2) * Bs + b] * Wfc[e + 2];
        a3 += h[(e + 3) * Bs + b] * Wfc[e + 3];
    }
    out[b] = a0 + a1 + a2 + a3 + bfc[0];
}

// ---------------------------------------------------------------------------
extern "C" void kernel_launch(void* const* d_in, const int* in_sizes, int n_in,
                              void* d_out, int out_size)
{
    const float* x    = (const float*)d_in[0];
    const float* Wih0 = (const float*)d_in[1];
    const float* Whh0 = (const float*)d_in[2];
    const float* bih0 = (const float*)d_in[3];
    const float* bhh0 = (const float*)d_in[4];
    const float* Wih1 = (const float*)d_in[5];
    const float* Whh1 = (const float*)d_in[6];
    const float* bih1 = (const float*)d_in[7];
    const float* bhh1 = (const float*)d_in[8];
    const float* Wfc  = (const float*)d_in[9];
    const float* bfc  = (const float*)d_in[10];
    float* out = (float*)d_out;

    static bool attr_set = false;
    if (!attr_set) {
        cudaFuncSetAttribute(lstm_main,
            cudaFuncAttributeMaxDynamicSharedMemorySize, SMEM_BYTES);
        attr_set = true;
    }

    init_states<<<512, 256>>>(x);
    lstm_main<<<NCTA, NT, SMEM_BYTES>>>(Wih0, Whh0, bih0, bhh0,
                                        Wih1, Whh1, bih1, bhh1);
    fc_kernel<<<Bs / 256, 256>>>(Wfc, bfc, out);
}

// round 3
// speedup vs baseline: 1.3483x; 1.3483x over previous
#include <cuda_runtime.h>
#include <cuda_bf16.h>

// ---------------------------------------------------------------------------
// Persistent-kernel 2-layer LSTM (H=256, B=512, T=512, D_IN=1) + final FC.
// 3 graph nodes. 128 CTAs x 256 threads (2 warps/SMSP for latency hiding),
// 1 CTA/SM. Weights (Whh0, Whh1, Wih1 slices) resident in SMEM all run.
// Double-buffered activation staging, one __syncthreads per K-chunk.
// Packed fma.rn.f32x2 math; h operands loaded as ld.shared.v2.b64.
// ---------------------------------------------------------------------------

#define Hs   256
#define Bs   512
#define Ts   512
#define HB   (Hs*Bs)

#define EL   16      // h-elems per CTA
#define BT   64      // batch per CTA
#define KC   64      // k-chunk
#define NT   256     // threads per CTA (8 warps)
#define NCTA 128

#define WSLICE (4*EL*Hs)                    // 16384 floats = 64KB
#define SMEM_FLOATS (3*WSLICE + 2*KC*BT)
#define SMEM_BYTES  (SMEM_FLOATS*4)         // 229376 B = 224KB

// ---- persistent device scratch --------------------------------------------
__device__ float g_h1s[2*HB];
__device__ float g_h2s[2*HB];
__device__ float g_xT[Ts*Bs];
__device__ unsigned g_arrive = 0;
__device__ unsigned g_gen    = 0;

// ---- helpers ---------------------------------------------------------------
typedef unsigned long long u64;

__device__ __forceinline__ u64 pack2(float a, float b) {
    u64 r; asm("mov.b64 %0, {%1,%2};" : "=l"(r) : "f"(a), "f"(b)); return r;
}
__device__ __forceinline__ void fma2(u64& d, u64 a, u64 b) {
    asm("fma.rn.f32x2 %0, %1, %2, %3;" : "=l"(d) : "l"(a), "l"(b), "l"(d));
}
__device__ __forceinline__ float2 unpack2(u64 v) {
    float2 r; asm("mov.b64 {%0,%1}, %2;" : "=f"(r.x), "=f"(r.y) : "l"(v)); return r;
}
__device__ __forceinline__ float tanh_ap(float x) {
    float y; asm("tanh.approx.f32 %0, %1;" : "=f"(y) : "f"(x)); return y;
}
__device__ __forceinline__ float sig_ap(float x) {
    return fmaf(tanh_ap(0.5f * x), 0.5f, 0.5f);
}

// ---- software grid barrier -------------------------------------------------
__device__ __forceinline__ void grid_barrier() {
    __syncthreads();
    if (threadIdx.x == 0) {
        __threadfence();
        unsigned my = atomicAdd(&g_gen, 0u);
        if (atomicAdd(&g_arrive, 1u) == NCTA - 1) {
            atomicExch(&g_arrive, 0u);
            __threadfence();
            atomicAdd(&g_gen, 1u);
        } else {
            while (atomicAdd(&g_gen, 0u) == my) { __nanosleep(32); }
        }
        __threadfence();
    }
    __syncthreads();
}

// ---------------------------------------------------------------------------
// Fused GEMM pipeline over NCH chunks of KC=64. Chunks 0..3 read (WA, sA),
// chunks 4..7 read (WB, sB). Hsh double-buffered; 1 sync per chunk.
// Thread (e, bg): gates i,f,g,o of elem e0+e for batches b0+bg*4 .. +3.
// W smem layout: [k][el][gate]  (k*64 + el*4 + g), 256B per k row.
// ---------------------------------------------------------------------------
template<int NCH>
__device__ __forceinline__ void gemm_run(
    const float* __restrict__ WA, const float* __restrict__ sA,
    const float* __restrict__ WB, const float* __restrict__ sB,
    u64 acc[4][2], float* __restrict__ Hb0, float* __restrict__ Hb1,
    int tid, int e, int bg, int b0)
{
    float4 pf[4];
    #pragma unroll
    for (int j = 0; j < 4; ++j) {
        int q = j * NT + tid;
        int k = q >> 4, c = q & 15;
        pf[j] = *(const float4*)&sA[(size_t)k * Bs + b0 + c * 4];
    }

    #pragma unroll
    for (int ch = 0; ch < NCH; ++ch) {
        float* Hb = (ch & 1) ? Hb1 : Hb0;
        #pragma unroll
        for (int j = 0; j < 4; ++j) {
            int q = j * NT + tid;
            int k = q >> 4, c = q & 15;
            *(float4*)&Hb[k * BT + c * 4] = pf[j];
        }
        __syncthreads();
        if (ch + 1 < NCH) {
            const float* s = (ch + 1 < 4) ? sA : sB;
            int kb = ((ch + 1) & 3) * KC;
            #pragma unroll
            for (int j = 0; j < 4; ++j) {
                int q = j * NT + tid;
                int k = q >> 4, c = q & 15;
                pf[j] = *(const float4*)&s[(size_t)(kb + k) * Bs + b0 + c * 4];
            }
        }
        const float* W  = (ch < 4) ? WA : WB;
        const float* Wk = W + ((ch & 3) * KC) * (4 * EL);
        unsigned hb_addr = (unsigned)__cvta_generic_to_shared(Hb) + (bg << 4);
        unsigned wb_addr = (unsigned)__cvta_generic_to_shared(Wk) + (e << 4);
        #pragma unroll 8
        for (int k = 0; k < KC; ++k) {
            float4 wv;
            asm("ld.shared.v4.f32 {%0,%1,%2,%3}, [%4];"
                : "=f"(wv.x), "=f"(wv.y), "=f"(wv.z), "=f"(wv.w)
                : "r"(wb_addr + (k << 8)));
            u64 h01, h23;
            asm("ld.shared.v2.b64 {%0,%1}, [%2];"
                : "=l"(h01), "=l"(h23) : "r"(hb_addr + (k << 8)));
            u64 w0 = pack2(wv.x, wv.x), w1 = pack2(wv.y, wv.y);
            u64 w2 = pack2(wv.z, wv.z), w3 = pack2(wv.w, wv.w);
            fma2(acc[0][0], w0, h01); fma2(acc[0][1], w0, h23);
            fma2(acc[1][0], w1, h01); fma2(acc[1][1], w1, h23);
            fma2(acc[2][0], w2, h01); fma2(acc[2][1], w2, h23);
            fma2(acc[3][0], w3, h01); fma2(acc[3][1], w3, h23);
        }
    }
}

__device__ __forceinline__ void zero_acc(u64 acc[4][2]) {
    #pragma unroll
    for (int g = 0; g < 4; ++g) { acc[g][0] = 0ull; acc[g][1] = 0ull; }
}

__device__ __forceinline__ void unpack_gates(u64 acc[4][2], float gate[4][4]) {
    #pragma unroll
    for (int g = 0; g < 4; ++g) {
        float2 a = unpack2(acc[g][0]);
        float2 b = unpack2(acc[g][1]);
        gate[g][0] = a.x; gate[g][1] = a.y;
        gate[g][2] = b.x; gate[g][3] = b.y;
    }
}

// load weight slice from global [4H x H] into smem [k][el][g]
__device__ __forceinline__ void load_wslice(
    float* __restrict__ Wsm, const float* __restrict__ Wg, int e0, int tid)
{
    for (int q = tid; q < WSLICE / 4; q += NT) {
        int re = q >> 6;                  // 0..63 = g*16+el
        int k4 = q & 63;
        int g  = re >> 4, el = re & 15;
        float4 v = *(const float4*)&Wg[(size_t)(g * Hs + e0 + el) * Hs + k4 * 4];
        Wsm[(k4 * 4 + 0) * 64 + el * 4 + g] = v.x;
        Wsm[(k4 * 4 + 1) * 64 + el * 4 + g] = v.y;
        Wsm[(k4 * 4 + 2) * 64 + el * 4 + g] = v.z;
        Wsm[(k4 * 4 + 3) * 64 + el * 4 + g] = v.w;
    }
}

// ---------------------------------------------------------------------------
__global__ void __launch_bounds__(NT, 1) lstm_main(
    const float* __restrict__ Wih0, const float* __restrict__ Whh0,
    const float* __restrict__ bih0, const float* __restrict__ bhh0,
    const float* __restrict__ Wih1, const float* __restrict__ Whh1,
    const float* __restrict__ bih1, const float* __restrict__ bhh1)
{
    extern __shared__ float sm[];
    float* W0  = sm;                 // Whh0 slice [k][el][g]
    float* W1h = sm + WSLICE;        // Whh1 slice
    float* W1x = sm + 2 * WSLICE;    // Wih1 slice
    float* Hb0 = sm + 3 * WSLICE;    // staging buf A [KC][BT]
    float* Hb1 = Hb0 + KC * BT;      // staging buf B

    const int tid = threadIdx.x;
    const int e   = tid >> 4;        // 0..15
    const int bg  = tid & 15;        // 0..15 (4 batches each)
    const int e0  = (blockIdx.x & 15) * EL;
    const int b0  = (blockIdx.x >> 4) * BT;
    const int eg  = e0 + e;
    const int bb  = b0 + bg * 4;

    load_wslice(W0,  Whh0, e0, tid);
    load_wslice(W1h, Whh1, e0, tid);
    load_wslice(W1x, Wih1, e0, tid);

    float wih0v[4], bias1[4], bias2[4];
    #pragma unroll
    for (int g = 0; g < 4; ++g) {
        int row = g * Hs + eg;
        wih0v[g] = Wih0[row];
        bias1[g] = bih0[row] + bhh0[row];
        bias2[g] = bih1[row] + bhh1[row];
    }
    float c1r[4] = {0.f, 0.f, 0.f, 0.f};
    float c2r[4] = {0.f, 0.f, 0.f, 0.f};

    u64 acc[4][2];
    float gate[4][4];

    for (int i = 0; i <= Ts; ++i) {
        // ---------------- layer 1, t = i ----------------
        if (i < Ts) {
            const float* hs = g_h1s + (size_t)(i & 1) * HB;
            float*       hd = g_h1s + (size_t)((i + 1) & 1) * HB;
            zero_acc(acc);
            gemm_run<4>(W0, hs, W0, hs, acc, Hb0, Hb1, tid, e, bg, b0);
            unpack_gates(acc, gate);

            float4 xv = *(const float4*)&g_xT[(size_t)i * Bs + bb];
            float xs[4] = {xv.x, xv.y, xv.z, xv.w};

            float hv[4];
            #pragma unroll
            for (int j = 0; j < 4; ++j) {
                float gi = fmaf(xs[j], wih0v[0], gate[0][j] + bias1[0]);
                float gf = fmaf(xs[j], wih0v[1], gate[1][j] + bias1[1]);
                float gg = fmaf(xs[j], wih0v[2], gate[2][j] + bias1[2]);
                float go = fmaf(xs[j], wih0v[3], gate[3][j] + bias1[3]);
                float iv = sig_ap(gi), fv = sig_ap(gf);
                float gv = tanh_ap(gg), ov = sig_ap(go);
                float c = fv * c1r[j] + iv * gv;
                c1r[j] = c;
                hv[j] = ov * tanh_ap(c);
            }
            *(float4*)&hd[(size_t)eg * Bs + bb] = make_float4(hv[0], hv[1], hv[2], hv[3]);
        }

        // ---------------- layer 2, t = i-1 (K=512 fused) ----------------
        if (i >= 1) {
            const float* h2s  = g_h2s + (size_t)((i - 1) & 1) * HB;
            float*       h2d  = g_h2s + (size_t)(i & 1) * HB;
            const float* h1in = g_h1s + (size_t)(i & 1) * HB;   // h1(t=i-1)
            zero_acc(acc);
            gemm_run<8>(W1h, h2s, W1x, h1in, acc, Hb0, Hb1, tid, e, bg, b0);
            unpack_gates(acc, gate);

            float hv[4];
            #pragma unroll
            for (int j = 0; j < 4; ++j) {
                float gi = gate[0][j] + bias2[0];
                float gf = gate[1][j] + bias2[1];
                float gg = gate[2][j] + bias2[2];
                float go = gate[3][j] + bias2[3];
                float iv = sig_ap(gi), fv = sig_ap(gf);
                float gv = tanh_ap(gg), ov = sig_ap(go);
                float c = fv * c2r[j] + iv * gv;
                c2r[j] = c;
                hv[j] = ov * tanh_ap(c);
            }
            *(float4*)&h2d[(size_t)eg * Bs + bb] = make_float4(hv[0], hv[1], hv[2], hv[3]);
        }

        grid_barrier();
    }
}

// ---------------------------------------------------------------------------
__global__ void init_states(const float* __restrict__ x) {
    int i0 = blockIdx.x * blockDim.x + threadIdx.x;
    int stride = gridDim.x * blockDim.x;
    for (int i = i0; i < 2 * HB; i += stride) g_h1s[i] = 0.0f;
    for (int i = i0; i < 2 * HB; i += stride) g_h2s[i] = 0.0f;
    for (int i = i0; i < Ts * Bs; i += stride) {
        int t = i / Bs, b = i % Bs;
        g_xT[i] = x[(size_t)b * Ts + t];
    }
}

__global__ void fc_kernel(const float* __restrict__ Wfc,
                          const float* __restrict__ bfc,
                          float* __restrict__ out)
{
    int b = blockIdx.x * blockDim.x + threadIdx.x;
    const float* h = g_h2s;   // final h2 in parity-0 buffer
    float a0 = 0.f, a1 = 0.f, a2 = 0.f, a3 = 0.f;
    #pragma unroll 4
    for (int e = 0; e < Hs; e += 4) {
        a0 += h[(e + 0) * Bs + b] * Wfc[e + 0];
        a1 += h[(e + 1) * Bs + b] * Wfc[e + 1];
        a2 += h[(e + 2) * Bs + b] * Wfc[e + 2];
        a3 += h[(e + 3) * Bs + b] * Wfc[e + 3];
    }
    out[b] = a0 + a1 + a2 + a3 + bfc[0];
}

// ---------------------------------------------------------------------------
extern "C" void kernel_launch(void* const* d_in, const int* in_sizes, int n_in,
                              void* d_out, int out_size)
{
    const float* x    = (const float*)d_in[0];
    const float* Wih0 = (const float*)d_in[1];
    const float* Whh0 = (const float*)d_in[2];
    const float* bih0 = (const float*)d_in[3];
    const float* bhh0 = (const float*)d_in[4];
    const float* Wih1 = (const float*)d_in[5];
    const float* Whh1 = (const float*)d_in[6];
    const float* bih1 = (const float*)d_in[7];
    const float* bhh1 = (const float*)d_in[8];
    const float* Wfc  = (const float*)d_in[9];
    const float* bfc  = (const float*)d_in[10];
    float* out = (float*)d_out;

    static bool attr_set = false;
    if (!attr_set) {
        cudaFuncSetAttribute(lstm_main,
            cudaFuncAttributeMaxDynamicSharedMemorySize, SMEM_BYTES);
        attr_set = true;
    }

    init_states<<<512, 256>>>(x);
    lstm_main<<<NCTA, NT, SMEM_BYTES>>>(Wih0, Whh0, bih0, bhh0,
                                        Wih1, Whh1, bih1, bhh1);
    fc_kernel<<<Bs / 256, 256>>>(Wfc, bfc, out);
}

// round 5
// speedup vs baseline: 2.3356x; 1.7322x over previous
#include <cuda_runtime.h>
#include <cuda_bf16.h>
#include <cstdint>

// ---------------------------------------------------------------------------
// Persistent 2-layer LSTM via mma.sync (HMMA) bf16 hi/lo-compensated GEMMs.
// 128 CTAs x 256 threads, 1 CTA/SM. Per CTA: 16 elems (64 gate-rows) x 64
// batch. Weights (Whh0/Whh1/Wih1 slices) resident in SMEM as bf16 hi/lo for
// the whole run. h in global as packed u32 (bf16 hi | lo<<16), [batch][elem].
// 3 graph nodes: init, persistent LSTM (software grid barrier), FC.
// ---------------------------------------------------------------------------

#define Hs   256
#define Bs   512
#define Ts   512
#define HB   (Hs*Bs)
#define NT   256
#define NCTA 128

// smem byte offsets
#define SM_W(w)   ((w)*65536)          // w-th weight: hi @+0 (32KB), lo @+32768
#define SM_B      196608               // B staging: buf i hi @+i*16384, lo @+8192
#define SM_DSM    196608               // D transpose buf (reuses B region) [64][68] f32
#define SM_BIAS1  229376
#define SM_BIAS2  229632
#define SM_W0     229888
#define SMEM_BYTES 230144

// ---- persistent device scratch --------------------------------------------
__device__ unsigned g_h1[2*HB];     // packed bf16 hi|lo<<16, [parity][batch][elem]
__device__ unsigned g_h2[2*HB];
__device__ float    g_xT[Ts*Bs];
__device__ unsigned g_arrive = 0;
__device__ unsigned g_gen    = 0;

// ---- helpers ---------------------------------------------------------------
__device__ __forceinline__ uint32_t smem_u32(const void* p) {
    uint32_t a;
    asm("{ .reg .u64 t; cvta.to.shared.u64 t, %1; cvt.u32.u64 %0, t; }"
        : "=r"(a) : "l"(p));
    return a;
}
__device__ __forceinline__ unsigned prmt(unsigned a, unsigned b, unsigned m) {
    unsigned r; asm("prmt.b32 %0,%1,%2,%3;" : "=r"(r) : "r"(a), "r"(b), "r"(m));
    return r;
}
__device__ __forceinline__ float tanh_ap(float x) {
    float y; asm("tanh.approx.f32 %0, %1;" : "=f"(y) : "f"(x)); return y;
}
__device__ __forceinline__ float sig_ap(float x) {
    return fmaf(tanh_ap(0.5f * x), 0.5f, 0.5f);
}
__device__ __forceinline__ void ldsm4(unsigned r[4], uint32_t addr) {
    asm volatile("ldmatrix.sync.aligned.m8n8.x4.shared.b16 {%0,%1,%2,%3}, [%4];"
        : "=r"(r[0]), "=r"(r[1]), "=r"(r[2]), "=r"(r[3]) : "r"(addr));
}
__device__ __forceinline__ void sts128(uint32_t addr, uint4 v) {
    asm volatile("st.shared.v4.b32 [%0], {%1,%2,%3,%4};"
        :: "r"(addr), "r"(v.x), "r"(v.y), "r"(v.z), "r"(v.w) : "memory");
}
__device__ __forceinline__ void mma_bf16(float d[4], const unsigned a[4],
                                         unsigned b0, unsigned b1) {
    asm volatile(
        "mma.sync.aligned.m16n8k16.row.col.f32.bf16.bf16.f32 "
        "{%0,%1,%2,%3}, {%4,%5,%6,%7}, {%8,%9}, {%0,%1,%2,%3};"
        : "+f"(d[0]), "+f"(d[1]), "+f"(d[2]), "+f"(d[3])
        : "r"(a[0]), "r"(a[1]), "r"(a[2]), "r"(a[3]), "r"(b0), "r"(b1));
}
__device__ __forceinline__ unsigned packbf(float a, float b) {
    return (unsigned)__bfloat16_as_ushort(__float2bfloat16(a))
         | ((unsigned)__bfloat16_as_ushort(__float2bfloat16(b)) << 16);
}

// ---- grid barrier ----------------------------------------------------------
__device__ __forceinline__ void grid_barrier() {
    __syncthreads();
    if (threadIdx.x == 0) {
        __threadfence();
        unsigned my = atomicAdd(&g_gen, 0u);
        if (atomicAdd(&g_arrive, 1u) == NCTA - 1) {
            atomicExch(&g_arrive, 0u);
            __threadfence();
            atomicAdd(&g_gen, 1u);
        } else {
            while (atomicAdd(&g_gen, 0u) == my) { __nanosleep(32); }
        }
        __threadfence();
    }
    __syncthreads();
}

// ---- B staging --------------------------------------------------------------
__device__ __forceinline__ void ldgB(uint4 pf[4], const unsigned* __restrict__ h,
                                     int b0, int kc) {
    int n = threadIdx.x >> 2, kq = (threadIdx.x & 3) * 16;
    const uint4* p = (const uint4*)(h + (size_t)(b0 + n) * Hs + kc * 64 + kq);
    pf[0] = p[0]; pf[1] = p[1]; pf[2] = p[2]; pf[3] = p[3];
}
__device__ __forceinline__ void stsB(uint32_t bufHi, const uint4 pf[4]) {
    int n = threadIdx.x >> 2;
    #pragma unroll
    for (int j = 0; j < 2; ++j) {
        int c = (threadIdx.x & 3) * 2 + j;
        uint32_t addr = bufHi + n * 128 + (((c + n) & 7) << 4);
        uint4 a = pf[2 * j], b = pf[2 * j + 1];
        uint4 hi = make_uint4(prmt(a.x, a.y, 0x5410), prmt(a.z, a.w, 0x5410),
                              prmt(b.x, b.y, 0x5410), prmt(b.z, b.w, 0x5410));
        uint4 lo = make_uint4(prmt(a.x, a.y, 0x7632), prmt(a.z, a.w, 0x7632),
                              prmt(b.x, b.y, 0x7632), prmt(b.z, b.w, 0x7632));
        sts128(addr, hi);
        sts128(addr + 8192, lo);
    }
}

// ---- MMA compute on one staged chunk (KC=64) -------------------------------
// aHi = smb + SM_W(w); bHi = staged buffer hi base. kcA = A k-chunk (0..3).
__device__ __forceinline__ void gemm_chunk(
    uint32_t aHi, uint32_t bHi, int kcA, float acc[4][4],
    int m_a, uint32_t aRowOff, int kh_a, int n_b, uint32_t bRowOff, int kh_b)
{
    #pragma unroll
    for (int ks = 0; ks < 4; ++ks) {
        unsigned ah[4], al[4], bh0[4], bh1[4], bl0[4], bl1[4];
        int ca = kcA * 8 + ks * 2 + kh_a;
        uint32_t aAddr = aHi + aRowOff + (((ca + m_a) & 31) << 4);
        ldsm4(ah, aAddr);
        ldsm4(al, aAddr + 32768);
        int cb = ks * 2 + kh_b;
        uint32_t bAddr = bHi + bRowOff + (((cb + n_b) & 7) << 4);
        ldsm4(bh0, bAddr);
        ldsm4(bh1, bAddr + 2048);          // n +16
        ldsm4(bl0, bAddr + 8192);          // lo plane
        ldsm4(bl1, bAddr + 8192 + 2048);
        // hi*hi
        mma_bf16(acc[0], ah, bh0[0], bh0[1]);
        mma_bf16(acc[1], ah, bh0[2], bh0[3]);
        mma_bf16(acc[2], ah, bh1[0], bh1[1]);
        mma_bf16(acc[3], ah, bh1[2], bh1[3]);
        // hi*lo
        mma_bf16(acc[0], ah, bl0[0], bl0[1]);
        mma_bf16(acc[1], ah, bl0[2], bl0[3]);
        mma_bf16(acc[2], ah, bl1[0], bl1[1]);
        mma_bf16(acc[3], ah, bl1[2], bl1[3]);
        // lo*hi
        mma_bf16(acc[0], al, bh0[0], bh0[1]);
        mma_bf16(acc[1], al, bh0[2], bh0[3]);
        mma_bf16(acc[2], al, bh1[0], bh1[1]);
        mma_bf16(acc[3], al, bh1[2], bh1[3]);
    }
}

// ---- epilogue (shared by both layers) ---------------------------------------
__device__ __forceinline__ void epilogue(
    float* __restrict__ Dsm, float acc[4][4], int m0, int wn,
    const float* __restrict__ bias_sm, const float* __restrict__ w0_sm,
    float xv, float cst[4], unsigned* __restrict__ hdst, int b0, int e0)
{
    const int tid = threadIdx.x, l = tid & 31;
    const int qrow = l >> 2, qcol = (l & 3) * 2;
    __syncthreads();                       // all warps done reading B region
    #pragma unroll
    for (int nt = 0; nt < 4; ++nt) {
        int col = wn * 32 + nt * 8 + qcol;
        *(float2*)&Dsm[(m0 + qrow) * 68 + col]     = make_float2(acc[nt][0], acc[nt][1]);
        *(float2*)&Dsm[(m0 + 8 + qrow) * 68 + col] = make_float2(acc[nt][2], acc[nt][3]);
    }
    __syncthreads();
    const int bl = tid & 63, eq = tid >> 6;
    unsigned pk[4];
    #pragma unroll
    for (int j = 0; j < 4; ++j) {
        int el = eq * 4 + j;
        float gi = Dsm[(el)      * 68 + bl] + bias_sm[el];
        float gf = Dsm[(16 + el) * 68 + bl] + bias_sm[16 + el];
        float gg = Dsm[(32 + el) * 68 + bl] + bias_sm[32 + el];
        float go = Dsm[(48 + el) * 68 + bl] + bias_sm[48 + el];
        if (w0_sm) {
            gi = fmaf(xv, w0_sm[el], gi);
            gf = fmaf(xv, w0_sm[16 + el], gf);
            gg = fmaf(xv, w0_sm[32 + el], gg);
            go = fmaf(xv, w0_sm[48 + el], go);
        }
        float iv = sig_ap(gi), fv = sig_ap(gf);
        float gv = tanh_ap(gg), ov = sig_ap(go);
        float c = fv * cst[j] + iv * gv;
        cst[j] = c;
        float h = ov * tanh_ap(c);
        float hh = __bfloat162float(__float2bfloat16(h));
        pk[j] = packbf(h, h - hh);
    }
    *(uint4*)&hdst[(size_t)(b0 + bl) * Hs + e0 + eq * 4] =
        make_uint4(pk[0], pk[1], pk[2], pk[3]);
    __syncthreads();
}

// ---------------------------------------------------------------------------
__global__ void __launch_bounds__(NT, 1) lstm_main(
    const float* __restrict__ Wih0, const float* __restrict__ Whh0,
    const float* __restrict__ bih0, const float* __restrict__ bhh0,
    const float* __restrict__ Wih1, const float* __restrict__ Whh1,
    const float* __restrict__ bih1, const float* __restrict__ bhh1)
{
    extern __shared__ char smc[];
    const uint32_t smb = smem_u32(smc);
    const int tid = threadIdx.x;
    const int mt  = blockIdx.x & 15;          // 16 m-tiles (16 elems each)
    const int e0  = mt * 16;
    const int b0  = (blockIdx.x >> 4) * 64;   // 8 n-tiles (64 batch each)

    // ---- load weight slices into smem (bf16 hi/lo, swizzled) ----
    {
        const float* Wg[3] = {Whh0, Whh1, Wih1};
        int m = tid >> 2;                      // 0..63 gate-row
        int g = m >> 4, el = m & 15;
        for (int w = 0; w < 3; ++w) {
            const float* row = Wg[w] + (size_t)(g * Hs + e0 + el) * Hs;
            uint32_t whi = smb + SM_W(w);
            #pragma unroll
            for (int c8 = 0; c8 < 8; ++c8) {
                int c = (tid & 3) * 8 + c8;    // chunk 0..31
                float4 v0 = *(const float4*)&row[c * 8];
                float4 v1 = *(const float4*)&row[c * 8 + 4];
                float h0 = __bfloat162float(__float2bfloat16(v0.x));
                float h1 = __bfloat162float(__float2bfloat16(v0.y));
                float h2 = __bfloat162float(__float2bfloat16(v0.z));
                float h3 = __bfloat162float(__float2bfloat16(v0.w));
                float h4 = __bfloat162float(__float2bfloat16(v1.x));
                float h5 = __bfloat162float(__float2bfloat16(v1.y));
                float h6 = __bfloat162float(__float2bfloat16(v1.z));
                float h7 = __bfloat162float(__float2bfloat16(v1.w));
                uint4 hi = make_uint4(packbf(v0.x, v0.y), packbf(v0.z, v0.w),
                                      packbf(v1.x, v1.y), packbf(v1.z, v1.w));
                uint4 lo = make_uint4(packbf(v0.x - h0, v0.y - h1),
                                      packbf(v0.z - h2, v0.w - h3),
                                      packbf(v1.x - h4, v1.y - h5),
                                      packbf(v1.z - h6, v1.w - h7));
                uint32_t addr = whi + m * 512 + (((c + m) & 31) << 4);
                sts128(addr, hi);
                sts128(addr + 32768, lo);
            }
        }
    }
    // biases + Wih0 column
    if (tid < 64) {
        int g = tid >> 4, el = tid & 15;
        int row = g * Hs + e0 + el;
        ((float*)(smc + SM_BIAS1))[tid] = bih0[row] + bhh0[row];
        ((float*)(smc + SM_BIAS2))[tid] = bih1[row] + bhh1[row];
        ((float*)(smc + SM_W0))[tid]    = Wih0[row];
    }
    __syncthreads();

    // lane constants for ldmatrix addressing
    const int wid = tid >> 5, l = tid & 31;
    const int wm = wid & 3, wn = wid >> 2;
    const int m0 = wm * 16;
    const int m_a = m0 + (l & 7) + (((l >> 3) & 1) << 3);
    const uint32_t aRowOff = m_a * 512;
    const int kh_a = l >> 4;
    const int n_b = (l & 7) + (((l >> 4) & 1) << 3);
    const uint32_t bRowOff = (wn * 32 + n_b) * 128;
    const int kh_b = (l >> 3) & 1;

    float* Dsm = (float*)(smc + SM_DSM);
    const float* bias1 = (const float*)(smc + SM_BIAS1);
    const float* bias2 = (const float*)(smc + SM_BIAS2);
    const float* w0sm  = (const float*)(smc + SM_W0);

    float c1[4] = {0.f, 0.f, 0.f, 0.f};
    float c2[4] = {0.f, 0.f, 0.f, 0.f};
    float acc[4][4];
    uint4 pf[4];

    for (int i = 0; i <= Ts; ++i) {
        const unsigned* h1p = g_h1 + (size_t)(i & 1) * HB;        // h1(t=i-1)
        unsigned*       h1d = g_h1 + (size_t)((i + 1) & 1) * HB;  // h1(t=i)
        const unsigned* h2p = g_h2 + (size_t)((i - 1) & 1) * HB;  // h2(t=i-2)
        unsigned*       h2d = g_h2 + (size_t)(i & 1) * HB;        // h2(t=i-1)

        // ---------------- layer 1 (t=i): K=256, Whh0 ----------------
        if (i < Ts) {
            #pragma unroll
            for (int nt = 0; nt < 4; ++nt)
                #pragma unroll
                for (int r = 0; r < 4; ++r) acc[nt][r] = 0.f;
            ldgB(pf, h1p, b0, 0);
            #pragma unroll
            for (int ch = 0; ch < 4; ++ch) {
                uint32_t buf = smb + SM_B + (ch & 1) * 16384;
                stsB(buf, pf);
                __syncthreads();
                if (ch < 3) ldgB(pf, h1p, b0, ch + 1);
                gemm_chunk(smb + SM_W(0), buf, ch, acc,
                           m_a, aRowOff, kh_a, n_b, bRowOff, kh_b);
            }
            float xv = g_xT[(size_t)i * Bs + b0 + (tid & 63)];
            epilogue(Dsm, acc, m0, wn, bias1, w0sm, xv, c1, h1d, b0, e0);
        }

        // ---------------- layer 2 (t=i-1): K=512, Whh1|Wih1 ----------
        if (i >= 1) {
            #pragma unroll
            for (int nt = 0; nt < 4; ++nt)
                #pragma unroll
                for (int r = 0; r < 4; ++r) acc[nt][r] = 0.f;
            ldgB(pf, h2p, b0, 0);
            #pragma unroll
            for (int ch = 0; ch < 8; ++ch) {
                uint32_t buf = smb + SM_B + (ch & 1) * 16384;
                stsB(buf, pf);
                __syncthreads();
                if (ch < 7) {
                    int nc = ch + 1;
                    if (nc < 4) ldgB(pf, h2p, b0, nc);
                    else        ldgB(pf, h1p, b0, nc - 4);
                }
                uint32_t wBase = (ch < 4) ? (smb + SM_W(1)) : (smb + SM_W(2));
                gemm_chunk(wBase, buf, ch & 3, acc,
                           m_a, aRowOff, kh_a, n_b, bRowOff, kh_b);
            }
            epilogue(Dsm, acc, m0, wn, bias2, (const float*)0, 0.f, c2, h2d, b0, e0);
        }

        grid_barrier();
    }
}

// ---------------------------------------------------------------------------
__global__ void init_states(const float* __restrict__ x) {
    int i0 = blockIdx.x * blockDim.x + threadIdx.x;
    int stride = gridDim.x * blockDim.x;
    for (int i = i0; i < 2 * HB; i += stride) { g_h1[i] = 0u; g_h2[i] = 0u; }
    for (int i = i0; i < Ts * Bs; i += stride) {
        int t = i / Bs, b = i % Bs;
        g_xT[i] = x[(size_t)b * Ts + t];
    }
}

__global__ void fc_kernel(const float* __restrict__ Wfc,
                          const float* __restrict__ bfc,
                          float* __restrict__ out)
{
    int b = blockIdx.x * blockDim.x + threadIdx.x;   // 0..511
    const unsigned* h = g_h2;    // final h2(t=511) in parity-0 buffer
    float acc = 0.f;
    #pragma unroll 8
    for (int e = 0; e < Hs; ++e) {
        unsigned p = h[(size_t)b * Hs + e];
        float hv = __bfloat162float(__ushort_as_bfloat16((unsigned short)(p & 0xffff)))
                 + __bfloat162float(__ushort_as_bfloat16((unsigned short)(p >> 16)));
        acc += hv * Wfc[e];
    }
    out[b] = acc + bfc[0];
}

// ---------------------------------------------------------------------------
extern "C" void kernel_launch(void* const* d_in, const int* in_sizes, int n_in,
                              void* d_out, int out_size)
{
    const float* x    = (const float*)d_in[0];
    const float* Wih0 = (const float*)d_in[1];
    const float* Whh0 = (const float*)d_in[2];
    const float* bih0 = (const float*)d_in[3];
    const float* bhh0 = (const float*)d_in[4];
    const float* Wih1 = (const float*)d_in[5];
    const float* Whh1 = (const float*)d_in[6];
    const float* bih1 = (const float*)d_in[7];
    const float* bhh1 = (const float*)d_in[8];
    const float* Wfc  = (const float*)d_in[9];
    const float* bfc  = (const float*)d_in[10];
    float* out = (float*)d_out;

    static bool attr_set = false;
    if (!attr_set) {
        cudaFuncSetAttribute(lstm_main,
            cudaFuncAttributeMaxDynamicSharedMemorySize, SMEM_BYTES);
        attr_set = true;
    }

    init_states<<<512, 256>>>(x);
    lstm_main<<<NCTA, NT, SMEM_BYTES>>>(Wih0, Whh0, bih0, bhh0,
                                        Wih1, Whh1, bih1, bhh1);
    fc_kernel<<<Bs / 256, 256>>>(Wfc, bfc, out);
}

// round 6
// speedup vs baseline: 3.6379x; 1.5576x over previous
#include <cuda_runtime.h>
#include <cuda_fp16.h>
#include <cstdint>

// ---------------------------------------------------------------------------
// Persistent 2-layer LSTM via mma.sync m16n8k16 fp16, 2-term compensation:
// W = W_hi + W_lo (fp16 pair, ~exact), h single fp16 (bounded in (-1,1)).
// 128 CTAs x 256 threads. CTA tile: 16 elems (64 gate-rows) x 64 batch.
// Weight slices resident in SMEM (fp16 hi/lo, 192KB). Fused 12-chunk pipeline
// per iteration: L1 (4 chunks, Whh0 x h1) -> L1 epilogue -> L2 (8 chunks,
// Whh1 x h2 | Wih1 x h1) -> L2 epilogue -> grid barrier.
// h stored fp16 [parity][batch][elem] in global (L2-coherent).
// ---------------------------------------------------------------------------

#define Hs   256
#define Bs   512
#define Ts   512
#define HB   (Hs*Bs)
#define NT   256
#define NCTA 128

// smem byte offsets
#define SM_W(w)   ((w)*65536)           // weight w: hi 32KB @+0, lo @+32768
#define SM_B      196608                // B staging: 2 bufs x 8192B
#define SM_DSM    212992                // transpose buf [64][68] f32 = 17408B
#define SM_BIAS1  230400
#define SM_BIAS2  230656
#define SM_W0     230912
#define SMEM_BYTES 231168

// ---- persistent device scratch --------------------------------------------
__device__ __half  g_h1[2*HB];          // [parity][batch][elem] fp16
__device__ __half  g_h2[2*HB];
__device__ float   g_xT[Ts*Bs];
__device__ unsigned g_arrive = 0;
__device__ unsigned g_gen    = 0;

// ---- helpers ---------------------------------------------------------------
__device__ __forceinline__ uint32_t smem_u32(const void* p) {
    uint32_t a;
    asm("{ .reg .u64 t; cvta.to.shared.u64 t, %1; cvt.u32.u64 %0, t; }"
        : "=r"(a) : "l"(p));
    return a;
}
__device__ __forceinline__ float tanh_ap(float x) {
    float y; asm("tanh.approx.f32 %0, %1;" : "=f"(y) : "f"(x)); return y;
}
__device__ __forceinline__ float sig_ap(float x) {
    return fmaf(tanh_ap(0.5f * x), 0.5f, 0.5f);
}
__device__ __forceinline__ void ldsm4(unsigned r[4], uint32_t addr) {
    asm volatile("ldmatrix.sync.aligned.m8n8.x4.shared.b16 {%0,%1,%2,%3}, [%4];"
        : "=r"(r[0]), "=r"(r[1]), "=r"(r[2]), "=r"(r[3]) : "r"(addr));
}
__device__ __forceinline__ void sts128(uint32_t addr, uint4 v) {
    asm volatile("st.shared.v4.b32 [%0], {%1,%2,%3,%4};"
        :: "r"(addr), "r"(v.x), "r"(v.y), "r"(v.z), "r"(v.w) : "memory");
}
__device__ __forceinline__ void mma_fp16(float d[4], const unsigned a[4],
                                         unsigned b0, unsigned b1) {
    asm volatile(
        "mma.sync.aligned.m16n8k16.row.col.f32.f16.f16.f32 "
        "{%0,%1,%2,%3}, {%4,%5,%6,%7}, {%8,%9}, {%0,%1,%2,%3};"
        : "+f"(d[0]), "+f"(d[1]), "+f"(d[2]), "+f"(d[3])
        : "r"(a[0]), "r"(a[1]), "r"(a[2]), "r"(a[3]), "r"(b0), "r"(b1));
}
__device__ __forceinline__ unsigned packh2(float a, float b) {
    return (unsigned)__half_as_ushort(__float2half_rn(a))
         | ((unsigned)__half_as_ushort(__float2half_rn(b)) << 16);
}

// ---- grid barrier ----------------------------------------------------------
__device__ __forceinline__ void grid_barrier() {
    __syncthreads();
    if (threadIdx.x == 0) {
        __threadfence();
        unsigned my = atomicAdd(&g_gen, 0u);
        if (atomicAdd(&g_arrive, 1u) == NCTA - 1) {
            atomicExch(&g_arrive, 0u);
            __threadfence();
            atomicAdd(&g_gen, 1u);
        } else {
            unsigned v;
            do {
                __nanosleep(32);
                asm volatile("ld.global.cg.u32 %0, [%1];"
                             : "=r"(v) : "l"(&g_gen));
            } while (v == my);
        }
        __threadfence();
    }
    __syncthreads();
}

// ---- B staging: chunk = n64 x k64 fp16 = 8KB -------------------------------
__device__ __forceinline__ void ldgB(uint4 pf[2], const __half* __restrict__ h,
                                     int b0, int kc) {
    int n = threadIdx.x >> 2;
    int c0 = (threadIdx.x & 3) * 2;
    const uint4* p = (const uint4*)(h + (size_t)(b0 + n) * Hs + kc * 64 + c0 * 8);
    pf[0] = p[0]; pf[1] = p[1];
}
__device__ __forceinline__ void stsB(uint32_t buf, const uint4 pf[2]) {
    int n = threadIdx.x >> 2;
    int c0 = (threadIdx.x & 3) * 2;
    sts128(buf + n * 128 + (((c0 + n) & 7) << 4), pf[0]);
    sts128(buf + n * 128 + (((c0 + 1 + n) & 7) << 4), pf[1]);
}

// ---- MMA on one staged chunk (KC=64): 2-term (W hi + W lo) x h -------------
__device__ __forceinline__ void gemm_chunk(
    uint32_t aHi, uint32_t bBuf, int kcA, float acc[4][4],
    int m_a, uint32_t aRowOff, int kh_a, int n_b, uint32_t bRowOff, int kh_b)
{
    #pragma unroll
    for (int ks = 0; ks < 4; ++ks) {
        unsigned ah[4], al[4], b0[4], b1[4];
        int ca = kcA * 8 + ks * 2 + kh_a;
        uint32_t aAddr = aHi + aRowOff + (((ca + m_a) & 31) << 4);
        ldsm4(ah, aAddr);
        ldsm4(al, aAddr + 32768);
        int cb = ks * 2 + kh_b;
        uint32_t bAddr = bBuf + bRowOff + (((cb + n_b) & 7) << 4);
        ldsm4(b0, bAddr);
        ldsm4(b1, bAddr + 2048);          // n +16
        mma_fp16(acc[0], ah, b0[0], b0[1]);
        mma_fp16(acc[1], ah, b0[2], b0[3]);
        mma_fp16(acc[2], ah, b1[0], b1[1]);
        mma_fp16(acc[3], ah, b1[2], b1[3]);
        mma_fp16(acc[0], al, b0[0], b0[1]);
        mma_fp16(acc[1], al, b0[2], b0[3]);
        mma_fp16(acc[2], al, b1[0], b1[1]);
        mma_fp16(acc[3], al, b1[2], b1[3]);
    }
}

// ---- epilogue ---------------------------------------------------------------
__device__ __forceinline__ void epilogue(
    float* __restrict__ Dsm, float acc[4][4], int m0, int wn,
    const float* __restrict__ bias_sm, const float* __restrict__ w0_sm,
    float xv, float cst[4], __half* __restrict__ hdst, int b0, int e0)
{
    const int tid = threadIdx.x, l = tid & 31;
    const int qrow = l >> 2, qcol = (l & 3) * 2;
    __syncthreads();
    #pragma unroll
    for (int nt = 0; nt < 4; ++nt) {
        int col = wn * 32 + nt * 8 + qcol;
        *(float2*)&Dsm[(m0 + qrow) * 68 + col]     = make_float2(acc[nt][0], acc[nt][1]);
        *(float2*)&Dsm[(m0 + 8 + qrow) * 68 + col] = make_float2(acc[nt][2], acc[nt][3]);
    }
    __syncthreads();
    const int bl = tid & 63, eq = tid >> 6;
    unsigned pk[2];
    #pragma unroll
    for (int jj = 0; jj < 2; ++jj) {
        float hv2[2];
        #pragma unroll
        for (int j2 = 0; j2 < 2; ++j2) {
            int j = jj * 2 + j2;
            int el = eq * 4 + j;
            float gi = Dsm[(el)      * 68 + bl] + bias_sm[el];
            float gf = Dsm[(16 + el) * 68 + bl] + bias_sm[16 + el];
            float gg = Dsm[(32 + el) * 68 + bl] + bias_sm[32 + el];
            float go = Dsm[(48 + el) * 68 + bl] + bias_sm[48 + el];
            if (w0_sm) {
                gi = fmaf(xv, w0_sm[el], gi);
                gf = fmaf(xv, w0_sm[16 + el], gf);
                gg = fmaf(xv, w0_sm[32 + el], gg);
                go = fmaf(xv, w0_sm[48 + el], go);
            }
            float iv = sig_ap(gi), fv = sig_ap(gf);
            float gv = tanh_ap(gg), ov = sig_ap(go);
            float c = fv * cst[j] + iv * gv;
            cst[j] = c;
            hv2[j2] = ov * tanh_ap(c);
        }
        pk[jj] = packh2(hv2[0], hv2[1]);
    }
    *(uint2*)&hdst[(size_t)(b0 + bl) * Hs + e0 + eq * 4] = make_uint2(pk[0], pk[1]);
    __syncthreads();
}

// ---------------------------------------------------------------------------
__global__ void __launch_bounds__(NT, 1) lstm_main(
    const float* __restrict__ Wih0, const float* __restrict__ Whh0,
    const float* __restrict__ bih0, const float* __restrict__ bhh0,
    const float* __restrict__ Wih1, const float* __restrict__ Whh1,
    const float* __restrict__ bih1, const float* __restrict__ bhh1)
{
    extern __shared__ char smc[];
    const uint32_t smb = smem_u32(smc);
    const int tid = threadIdx.x;
    const int mt  = blockIdx.x & 15;
    const int e0  = mt * 16;
    const int b0  = (blockIdx.x >> 4) * 64;

    // ---- load weight slices into smem (fp16 hi/lo, swizzled) ----
    {
        const float* Wg[3] = {Whh0, Whh1, Wih1};
        int m = tid >> 2;                     // gate-row 0..63
        int g = m >> 4, el = m & 15;
        for (int w = 0; w < 3; ++w) {
            const float* row = Wg[w] + (size_t)(g * Hs + e0 + el) * Hs;
            uint32_t whi = smb + SM_W(w);
            #pragma unroll
            for (int c8 = 0; c8 < 8; ++c8) {
                int c = (tid & 3) * 8 + c8;   // 16B-chunk 0..31
                float4 v0 = *(const float4*)&row[c * 8];
                float4 v1 = *(const float4*)&row[c * 8 + 4];
                float r0 = __half2float(__float2half_rn(v0.x));
                float r1 = __half2float(__float2half_rn(v0.y));
                float r2 = __half2float(__float2half_rn(v0.z));
                float r3 = __half2float(__float2half_rn(v0.w));
                float r4 = __half2float(__float2half_rn(v1.x));
                float r5 = __half2float(__float2half_rn(v1.y));
                float r6 = __half2float(__float2half_rn(v1.z));
                float r7 = __half2float(__float2half_rn(v1.w));
                uint4 hi = make_uint4(packh2(v0.x, v0.y), packh2(v0.z, v0.w),
                                      packh2(v1.x, v1.y), packh2(v1.z, v1.w));
                uint4 lo = make_uint4(packh2(v0.x - r0, v0.y - r1),
                                      packh2(v0.z - r2, v0.w - r3),
                                      packh2(v1.x - r4, v1.y - r5),
                                      packh2(v1.z - r6, v1.w - r7));
                uint32_t addr = whi + m * 512 + (((c + m) & 31) << 4);
                sts128(addr, hi);
                sts128(addr + 32768, lo);
            }
        }
    }
    if (tid < 64) {
        int g = tid >> 4, el = tid & 15;
        int row = g * Hs + e0 + el;
        ((float*)(smc + SM_BIAS1))[tid] = bih0[row] + bhh0[row];
        ((float*)(smc + SM_BIAS2))[tid] = bih1[row] + bhh1[row];
        ((float*)(smc + SM_W0))[tid]    = Wih0[row];
    }
    __syncthreads();

    // lane constants for ldmatrix addressing
    const int wid = tid >> 5, l = tid & 31;
    const int wm = wid & 3, wn = wid >> 2;
    const int m0 = wm * 16;
    const int m_a = m0 + (l & 7) + (((l >> 3) & 1) << 3);
    const uint32_t aRowOff = m_a * 512;
    const int kh_a = l >> 4;
    const int n_b = (l & 7) + (((l >> 4) & 1) << 3);
    const uint32_t bRowOff = (wn * 32 + n_b) * 128;
    const int kh_b = (l >> 3) & 1;

    float* Dsm = (float*)(smc + SM_DSM);
    const float* bias1 = (const float*)(smc + SM_BIAS1);
    const float* bias2 = (const float*)(smc + SM_BIAS2);
    const float* w0sm  = (const float*)(smc + SM_W0);

    float c1[4] = {0.f, 0.f, 0.f, 0.f};
    float c2[4] = {0.f, 0.f, 0.f, 0.f};
    float acc[4][4];
    uint4 pf[2];

    for (int i = 0; i <= Ts; ++i) {
        const __half* h1p = g_h1 + (size_t)(i & 1) * HB;        // h1(t=i-1)
        __half*       h1d = g_h1 + (size_t)((i + 1) & 1) * HB;  // h1(t=i)
        const __half* h2p = g_h2 + (size_t)((i + 1) & 1) * HB;  // h2(t=i-2)
        __half*       h2d = g_h2 + (size_t)(i & 1) * HB;        // h2(t=i-1)

        const int chBeg = (i < Ts) ? 0 : 4;
        const int chEnd = (i >= 1) ? 12 : 4;
        float xv = (i < Ts) ? g_xT[(size_t)i * Bs + b0 + (tid & 63)] : 0.f;

        #pragma unroll
        for (int nt = 0; nt < 4; ++nt)
            #pragma unroll
            for (int r = 0; r < 4; ++r) acc[nt][r] = 0.f;

        // fused chunk pipeline: ch 0-3 = L1 (Whh0 x h1p), 4-7 = Whh1 x h2p,
        // 8-11 = Wih1 x h1p. All inputs available at iter start.
        ldgB(pf, (chBeg >= 4 && chBeg < 8) ? h2p : h1p, b0, chBeg & 3);
        #pragma unroll 1
        for (int ch = chBeg; ch < chEnd; ++ch) {
            uint32_t buf = smb + SM_B + (ch & 1) * 8192;
            stsB(buf, pf);
            __syncthreads();
            if (ch + 1 < chEnd) {
                int nc = ch + 1;
                ldgB(pf, (nc >= 4 && nc < 8) ? h2p : h1p, b0, nc & 3);
            }
            uint32_t wBase = smb + SM_W(ch < 4 ? 0 : (ch < 8 ? 1 : 2));
            gemm_chunk(wBase, buf, ch & 3, acc,
                       m_a, aRowOff, kh_a, n_b, bRowOff, kh_b);
            if (ch == 3) {
                epilogue(Dsm, acc, m0, wn, bias1, w0sm, xv, c1, h1d, b0, e0);
                #pragma unroll
                for (int nt = 0; nt < 4; ++nt)
                    #pragma unroll
                    for (int r = 0; r < 4; ++r) acc[nt][r] = 0.f;
            }
        }
        if (i >= 1)
            epilogue(Dsm, acc, m0, wn, bias2, (const float*)0, 0.f, c2, h2d, b0, e0);

        grid_barrier();
    }
}

// ---------------------------------------------------------------------------
__global__ void init_states(const float* __restrict__ x) {
    int i0 = blockIdx.x * blockDim.x + threadIdx.x;
    int stride = gridDim.x * blockDim.x;
    unsigned* z1 = (unsigned*)g_h1;
    unsigned* z2 = (unsigned*)g_h2;
    for (int i = i0; i < HB; i += stride) { z1[i] = 0u; z2[i] = 0u; }
    for (int i = i0; i < Ts * Bs; i += stride) {
        int t = i / Bs, b = i % Bs;
        g_xT[i] = x[(size_t)b * Ts + t];
    }
}

__global__ void fc_kernel(const float* __restrict__ Wfc,
                          const float* __restrict__ bfc,
                          float* __restrict__ out)
{
    int b = blockIdx.x * blockDim.x + threadIdx.x;   // 0..511
    const __half* h = g_h2;   // final h2(t=511) in parity-0 buffer
    float acc = 0.f;
    #pragma unroll 8
    for (int e = 0; e < Hs; ++e)
        acc += __half2float(h[(size_t)b * Hs + e]) * Wfc[e];
    out[b] = acc + bfc[0];
}

// ---------------------------------------------------------------------------
extern "C" void kernel_launch(void* const* d_in, const int* in_sizes, int n_in,
                              void* d_out, int out_size)
{
    const float* x    = (const float*)d_in[0];
    const float* Wih0 = (const float*)d_in[1];
    const float* Whh0 = (const float*)d_in[2];
    const float* bih0 = (const float*)d_in[3];
    const float* bhh0 = (const float*)d_in[4];
    const float* Wih1 = (const float*)d_in[5];
    const float* Whh1 = (const float*)d_in[6];
    const float* bih1 = (const float*)d_in[7];
    const float* bhh1 = (const float*)d_in[8];
    const float* Wfc  = (const float*)d_in[9];
    const float* bfc  = (const float*)d_in[10];
    float* out = (float*)d_out;

    static bool attr_set = false;
    if (!attr_set) {
        cudaFuncSetAttribute(lstm_main,
            cudaFuncAttributeMaxDynamicSharedMemorySize, SMEM_BYTES);
        attr_set = true;
    }

    init_states<<<512, 256>>>(x);
    lstm_main<<<NCTA, NT, SMEM_BYTES>>>(Wih0, Whh0, bih0, bhh0,
                                        Wih1, Whh1, bih1, bhh1);
    fc_kernel<<<Bs / 256, 256>>>(Wfc, bfc, out);
}

// round 7
// speedup vs baseline: 3.9102x; 1.0749x over previous
#include <cuda_runtime.h>
#include <cuda_fp16.h>
#include <cstdint>

// ---------------------------------------------------------------------------
// Persistent 2-layer LSTM via mma.sync m16n8k16 fp16, 2-term compensation:
// W = W_hi + W_lo (fp16 pair, ~exact), h single fp16 (bounded in (-1,1)).
// 128 CTAs x 256 threads. CTA tile: 16 elems (64 gate-rows) x 64 batch.
// Weight slices resident in SMEM (fp16 hi/lo, 192KB).
//
// The 8 batch-groups (nt = blockIdx>>4) are fully independent: CTA (mt,nt)
// writes h only for batches [nt*64, nt*64+64) and reads h only from CTAs of
// the same nt. So the inter-step barrier is PER-GROUP (16 CTAs), not global.
// ---------------------------------------------------------------------------

#define Hs   256
#define Bs   512
#define Ts   512
#define HB   (Hs*Bs)
#define NT   256
#define NCTA 128

// smem byte offsets
#define SM_W(w)   ((w)*65536)           // weight w: hi 32KB @+0, lo @+32768
#define SM_B      196608                // B staging: 2 bufs x 8192B
#define SM_DSM    212992                // transpose buf [64][68] f32 = 17408B
#define SM_BIAS1  230400
#define SM_BIAS2  230656
#define SM_W0     230912
#define SMEM_BYTES 231168

// ---- persistent device scratch --------------------------------------------
__device__ __half  g_h1[2*HB];          // [parity][batch][elem] fp16
__device__ __half  g_h2[2*HB];
__device__ float   g_xT[Ts*Bs];
__device__ unsigned g_garr[8*128];      // per-group arrive counters (512B apart)
__device__ unsigned g_ggen[8*128];      // per-group generation counters

// ---- helpers ---------------------------------------------------------------
__device__ __forceinline__ uint32_t smem_u32(const void* p) {
    uint32_t a;
    asm("{ .reg .u64 t; cvta.to.shared.u64 t, %1; cvt.u32.u64 %0, t; }"
        : "=r"(a) : "l"(p));
    return a;
}
__device__ __forceinline__ float tanh_ap(float x) {
    float y; asm("tanh.approx.f32 %0, %1;" : "=f"(y) : "f"(x)); return y;
}
__device__ __forceinline__ float sig_ap(float x) {
    return fmaf(tanh_ap(0.5f * x), 0.5f, 0.5f);
}
__device__ __forceinline__ void ldsm4(unsigned r[4], uint32_t addr) {
    asm volatile("ldmatrix.sync.aligned.m8n8.x4.shared.b16 {%0,%1,%2,%3}, [%4];"
        : "=r"(r[0]), "=r"(r[1]), "=r"(r[2]), "=r"(r[3]) : "r"(addr));
}
__device__ __forceinline__ void sts128(uint32_t addr, uint4 v) {
    asm volatile("st.shared.v4.b32 [%0], {%1,%2,%3,%4};"
        :: "r"(addr), "r"(v.x), "r"(v.y), "r"(v.z), "r"(v.w) : "memory");
}
__device__ __forceinline__ void mma_fp16(float d[4], const unsigned a[4],
                                         unsigned b0, unsigned b1) {
    asm volatile(
        "mma.sync.aligned.m16n8k16.row.col.f32.f16.f16.f32 "
        "{%0,%1,%2,%3}, {%4,%5,%6,%7}, {%8,%9}, {%0,%1,%2,%3};"
        : "+f"(d[0]), "+f"(d[1]), "+f"(d[2]), "+f"(d[3])
        : "r"(a[0]), "r"(a[1]), "r"(a[2]), "r"(a[3]), "r"(b0), "r"(b1));
}
__device__ __forceinline__ unsigned packh2(float a, float b) {
    return (unsigned)__half_as_ushort(__float2half_rn(a))
         | ((unsigned)__half_as_ushort(__float2half_rn(b)) << 16);
}

// ---- per-group (16 CTA) barrier --------------------------------------------
__device__ __forceinline__ void group_barrier(int grp) {
    __syncthreads();
    if (threadIdx.x == 0) {
        unsigned* arr = &g_garr[grp * 128];
        unsigned* gen = &g_ggen[grp * 128];
        __threadfence();                          // order h writes (gpu scope)
        unsigned my;
        asm volatile("ld.acquire.gpu.global.u32 %0, [%1];"
                     : "=r"(my) : "l"(gen));
        if (atomicAdd(arr, 1u) == 15u) {
            atomicExch(arr, 0u);
            __threadfence();                      // order reset before release
            atomicAdd(gen, 1u);
        } else {
            unsigned v;
            do {
                __nanosleep(16);
                asm volatile("ld.acquire.gpu.global.u32 %0, [%1];"
                             : "=r"(v) : "l"(gen));
            } while (v == my);
        }
    }
    __syncthreads();
}

// ---- B staging: chunk = n64 x k64 fp16 = 8KB -------------------------------
__device__ __forceinline__ void ldgB(uint4 pf[2], const __half* __restrict__ h,
                                     int b0, int kc) {
    int n = threadIdx.x >> 2;
    int c0 = (threadIdx.x & 3) * 2;
    const uint4* p = (const uint4*)(h + (size_t)(b0 + n) * Hs + kc * 64 + c0 * 8);
    pf[0] = __ldcg(p);
    pf[1] = __ldcg(p + 1);
}
__device__ __forceinline__ void stsB(uint32_t buf, const uint4 pf[2]) {
    int n = threadIdx.x >> 2;
    int c0 = (threadIdx.x & 3) * 2;
    sts128(buf + n * 128 + (((c0 + n) & 7) << 4), pf[0]);
    sts128(buf + n * 128 + (((c0 + 1 + n) & 7) << 4), pf[1]);
}

// ---- MMA on one staged chunk (KC=64): 2-term (W hi + W lo) x h -------------
__device__ __forceinline__ void gemm_chunk(
    uint32_t aHi, uint32_t bBuf, int kcA, float acc[4][4],
    int m_a, uint32_t aRowOff, int kh_a, int n_b, uint32_t bRowOff, int kh_b)
{
    #pragma unroll
    for (int ks = 0; ks < 4; ++ks) {
        unsigned ah[4], al[4], b0[4], b1[4];
        int ca = kcA * 8 + ks * 2 + kh_a;
        uint32_t aAddr = aHi + aRowOff + (((ca + m_a) & 31) << 4);
        ldsm4(ah, aAddr);
        ldsm4(al, aAddr + 32768);
        int cb = ks * 2 + kh_b;
        uint32_t bAddr = bBuf + bRowOff + (((cb + n_b) & 7) << 4);
        ldsm4(b0, bAddr);
        ldsm4(b1, bAddr + 2048);          // n +16
        mma_fp16(acc[0], ah, b0[0], b0[1]);
        mma_fp16(acc[1], ah, b0[2], b0[3]);
        mma_fp16(acc[2], ah, b1[0], b1[1]);
        mma_fp16(acc[3], ah, b1[2], b1[3]);
        mma_fp16(acc[0], al, b0[0], b0[1]);
        mma_fp16(acc[1], al, b0[2], b0[3]);
        mma_fp16(acc[2], al, b1[0], b1[1]);
        mma_fp16(acc[3], al, b1[2], b1[3]);
    }
}

// ---- epilogue: ONE internal sync --------------------------------------------
// Safe because Dsm is a dedicated region: Dsm writes can overlap other warps
// still reading B/W smem in gemm_chunk; the mid-sync orders all Dsm writes
// before reads; buf-reuse after the epilogue is ordered by the next chunk
// sync (a warp reaches it only after finishing its epilogue compute).
__device__ __forceinline__ void epilogue(
    float* __restrict__ Dsm, float acc[4][4], int m0, int wn,
    const float* __restrict__ bias_sm, const float* __restrict__ w0_sm,
    float xv, float cst[4], __half* __restrict__ hdst, int b0, int e0)
{
    const int tid = threadIdx.x, l = tid & 31;
    const int qrow = l >> 2, qcol = (l & 3) * 2;
    #pragma unroll
    for (int nt = 0; nt < 4; ++nt) {
        int col = wn * 32 + nt * 8 + qcol;
        *(float2*)&Dsm[(m0 + qrow) * 68 + col]     = make_float2(acc[nt][0], acc[nt][1]);
        *(float2*)&Dsm[(m0 + 8 + qrow) * 68 + col] = make_float2(acc[nt][2], acc[nt][3]);
    }
    __syncthreads();
    const int bl = tid & 63, eq = tid >> 6;
    unsigned pk[2];
    #pragma unroll
    for (int jj = 0; jj < 2; ++jj) {
        float hv2[2];
        #pragma unroll
        for (int j2 = 0; j2 < 2; ++j2) {
            int j = jj * 2 + j2;
            int el = eq * 4 + j;
            float gi = Dsm[(el)      * 68 + bl] + bias_sm[el];
            float gf = Dsm[(16 + el) * 68 + bl] + bias_sm[16 + el];
            float gg = Dsm[(32 + el) * 68 + bl] + bias_sm[32 + el];
            float go = Dsm[(48 + el) * 68 + bl] + bias_sm[48 + el];
            if (w0_sm) {
                gi = fmaf(xv, w0_sm[el], gi);
                gf = fmaf(xv, w0_sm[16 + el], gf);
                gg = fmaf(xv, w0_sm[32 + el], gg);
                go = fmaf(xv, w0_sm[48 + el], go);
            }
            float iv = sig_ap(gi), fv = sig_ap(gf);
            float gv = tanh_ap(gg), ov = sig_ap(go);
            float c = fv * cst[j] + iv * gv;
            cst[j] = c;
            hv2[j2] = ov * tanh_ap(c);
        }
        pk[jj] = packh2(hv2[0], hv2[1]);
    }
    *(uint2*)&hdst[(size_t)(b0 + bl) * Hs + e0 + eq * 4] = make_uint2(pk[0], pk[1]);
}

// ---------------------------------------------------------------------------
__global__ void __launch_bounds__(NT, 1) lstm_main(
    const float* __restrict__ Wih0, const float* __restrict__ Whh0,
    const float* __restrict__ bih0, const float* __restrict__ bhh0,
    const float* __restrict__ Wih1, const float* __restrict__ Whh1,
    const float* __restrict__ bih1, const float* __restrict__ bhh1)
{
    extern __shared__ char smc[];
    const uint32_t smb = smem_u32(smc);
    const int tid = threadIdx.x;
    const int mt  = blockIdx.x & 15;
    const int grp = blockIdx.x >> 4;
    const int e0  = mt * 16;
    const int b0  = grp * 64;

    // ---- load weight slices into smem (fp16 hi/lo, swizzled) ----
    {
        const float* Wg[3] = {Whh0, Whh1, Wih1};
        int m = tid >> 2;                     // gate-row 0..63
        int g = m >> 4, el = m & 15;
        for (int w = 0; w < 3; ++w) {
            const float* row = Wg[w] + (size_t)(g * Hs + e0 + el) * Hs;
            uint32_t whi = smb + SM_W(w);
            #pragma unroll
            for (int c8 = 0; c8 < 8; ++c8) {
                int c = (tid & 3) * 8 + c8;   // 16B-chunk 0..31
                float4 v0 = *(const float4*)&row[c * 8];
                float4 v1 = *(const float4*)&row[c * 8 + 4];
                float r0 = __half2float(__float2half_rn(v0.x));
                float r1 = __half2float(__float2half_rn(v0.y));
                float r2 = __half2float(__float2half_rn(v0.z));
                float r3 = __half2float(__float2half_rn(v0.w));
                float r4 = __half2float(__float2half_rn(v1.x));
                float r5 = __half2float(__float2half_rn(v1.y));
                float r6 = __half2float(__float2half_rn(v1.z));
                float r7 = __half2float(__float2half_rn(v1.w));
                uint4 hi = make_uint4(packh2(v0.x, v0.y), packh2(v0.z, v0.w),
                                      packh2(v1.x, v1.y), packh2(v1.z, v1.w));
                uint4 lo = make_uint4(packh2(v0.x - r0, v0.y - r1),
                                      packh2(v0.z - r2, v0.w - r3),
                                      packh2(v1.x - r4, v1.y - r5),
                                      packh2(v1.z - r6, v1.w - r7));
                uint32_t addr = whi + m * 512 + (((c + m) & 31) << 4);
                sts128(addr, hi);
                sts128(addr + 32768, lo);
            }
        }
    }
    if (tid < 64) {
        int g = tid >> 4, el = tid & 15;
        int row = g * Hs + e0 + el;
        ((float*)(smc + SM_BIAS1))[tid] = bih0[row] + bhh0[row];
        ((float*)(smc + SM_BIAS2))[tid] = bih1[row] + bhh1[row];
        ((float*)(smc + SM_W0))[tid]    = Wih0[row];
    }
    __syncthreads();

    // lane constants for ldmatrix addressing
    const int wid = tid >> 5, l = tid & 31;
    const int wm = wid & 3, wn = wid >> 2;
    const int m0 = wm * 16;
    const int m_a = m0 + (l & 7) + (((l >> 3) & 1) << 3);
    const uint32_t aRowOff = m_a * 512;
    const int kh_a = l >> 4;
    const int n_b = (l & 7) + (((l >> 4) & 1) << 3);
    const uint32_t bRowOff = (wn * 32 + n_b) * 128;
    const int kh_b = (l >> 3) & 1;

    float* Dsm = (float*)(smc + SM_DSM);
    const float* bias1 = (const float*)(smc + SM_BIAS1);
    const float* bias2 = (const float*)(smc + SM_BIAS2);
    const float* w0sm  = (const float*)(smc + SM_W0);

    float c1[4] = {0.f, 0.f, 0.f, 0.f};
    float c2[4] = {0.f, 0.f, 0.f, 0.f};
    float acc[4][4];
    uint4 pf[2];

    for (int i = 0; i <= Ts; ++i) {
        const __half* h1p = g_h1 + (size_t)(i & 1) * HB;        // h1(t=i-1)
        __half*       h1d = g_h1 + (size_t)((i + 1) & 1) * HB;  // h1(t=i)
        const __half* h2p = g_h2 + (size_t)((i + 1) & 1) * HB;  // h2(t=i-2)
        __half*       h2d = g_h2 + (size_t)(i & 1) * HB;        // h2(t=i-1)

        const int chBeg = (i < Ts) ? 0 : 4;
        const int chEnd = (i >= 1) ? 12 : 4;
        float xv = (i < Ts) ? g_xT[(size_t)i * Bs + b0 + (tid & 63)] : 0.f;

        #pragma unroll
        for (int nt = 0; nt < 4; ++nt)
            #pragma unroll
            for (int r = 0; r < 4; ++r) acc[nt][r] = 0.f;

        // fused chunk pipeline: ch 0-3 = L1 (Whh0 x h1p), 4-7 = Whh1 x h2p,
        // 8-11 = Wih1 x h1p. All inputs available at iter start.
        ldgB(pf, (chBeg >= 4 && chBeg < 8) ? h2p : h1p, b0, chBeg & 3);
        #pragma unroll 1
        for (int ch = chBeg; ch < chEnd; ++ch) {
            uint32_t buf = smb + SM_B + (ch & 1) * 8192;
            stsB(buf, pf);
            __syncthreads();
            if (ch + 1 < chEnd) {
                int nc = ch + 1;
                ldgB(pf, (nc >= 4 && nc < 8) ? h2p : h1p, b0, nc & 3);
            }
            uint32_t wBase = smb + SM_W(ch < 4 ? 0 : (ch < 8 ? 1 : 2));
            gemm_chunk(wBase, buf, ch & 3, acc,
                       m_a, aRowOff, kh_a, n_b, bRowOff, kh_b);
            if (ch == 3) {
                epilogue(Dsm, acc, m0, wn, bias1, w0sm, xv, c1, h1d, b0, e0);
                #pragma unroll
                for (int nt = 0; nt < 4; ++nt)
                    #pragma unroll
                    for (int r = 0; r < 4; ++r) acc[nt][r] = 0.f;
            }
        }
        if (i >= 1)
            epilogue(Dsm, acc, m0, wn, bias2, (const float*)0, 0.f, c2, h2d, b0, e0);

        group_barrier(grp);
    }
}

// ---------------------------------------------------------------------------
__global__ void init_states(const float* __restrict__ x) {
    int i0 = blockIdx.x * blockDim.x + threadIdx.x;
    int stride = gridDim.x * blockDim.x;
    unsigned* z1 = (unsigned*)g_h1;
    unsigned* z2 = (unsigned*)g_h2;
    for (int i = i0; i < HB; i += stride) { z1[i] = 0u; z2[i] = 0u; }
    for (int i = i0; i < 8 * 128; i += stride) { g_garr[i] = 0u; g_ggen[i] = 0u; }
    for (int i = i0; i < Ts * Bs; i += stride) {
        int t = i / Bs, b = i % Bs;
        g_xT[i] = x[(size_t)b * Ts + t];
    }
}

__global__ void fc_kernel(const float* __restrict__ Wfc,
                          const float* __restrict__ bfc,
                          float* __restrict__ out)
{
    int b = blockIdx.x * blockDim.x + threadIdx.x;   // 0..511
    const __half* h = g_h2;   // final h2(t=511) in parity-0 buffer
    float acc = 0.f;
    #pragma unroll 8
    for (int e = 0; e < Hs; ++e)
        acc += __half2float(h[(size_t)b * Hs + e]) * Wfc[e];
    out[b] = acc + bfc[0];
}

// ---------------------------------------------------------------------------
extern "C" void kernel_launch(void* const* d_in, const int* in_sizes, int n_in,
                              void* d_out, int out_size)
{
    const float* x    = (const float*)d_in[0];
    const float* Wih0 = (const float*)d_in[1];
    const float* Whh0 = (const float*)d_in[2];
    const float* bih0 = (const float*)d_in[3];
    const float* bhh0 = (const float*)d_in[4];
    const float* Wih1 = (const float*)d_in[5];
    const float* Whh1 = (const float*)d_in[6];
    const float* bih1 = (const float*)d_in[7];
    const float* bhh1 = (const float*)d_in[8];
    const float* Wfc  = (const float*)d_in[9];
    const float* bfc  = (const float*)d_in[10];
    float* out = (float*)d_out;

    static bool attr_set = false;
    if (!attr_set) {
        cudaFuncSetAttribute(lstm_main,
            cudaFuncAttributeMaxDynamicSharedMemorySize, SMEM_BYTES);
        attr_set = true;
    }

    init_states<<<512, 256>>>(x);
    lstm_main<<<NCTA, NT, SMEM_BYTES>>>(Wih0, Whh0, bih0, bhh0,
                                        Wih1, Whh1, bih1, bhh1);
    fc_kernel<<<Bs / 256, 256>>>(Wfc, bfc, out);
}

// round 8
// speedup vs baseline: 3.9720x; 1.0158x over previous
#include <cuda_runtime.h>
#include <cuda_fp16.h>
#include <cstdint>

// ---------------------------------------------------------------------------
// Persistent 2-layer LSTM via mma.sync m16n8k16 fp16 (single-plane weights,
// h fp16). 128 CTAs x 256 threads. CTA tile: 16 elems (64 gate-rows) x 64
// batch. Weight slices resident in SMEM (fp16, 96KB). KC=128 B-staging
// chunks (6 per iteration), double-buffered. Per-batch-group (16 CTA)
// inter-step barrier. h stored fp16 [parity][batch][elem] in global.
// ---------------------------------------------------------------------------

#define Hs   256
#define Bs   512
#define Ts   512
#define HB   (Hs*Bs)
#define NT   256
#define NCTA 128

// smem byte offsets
#define SM_W(w)   ((w)*32768)           // weight w: 64 rows x 256k fp16 = 32KB
#define SM_B      98304                 // B staging: 2 bufs x 16384B
#define SM_DSM    131072                // transpose buf [64][68] f32 = 17408B
#define SM_BIAS1  148480
#define SM_BIAS2  148736
#define SM_W0     148992
#define SMEM_BYTES 149248

// ---- persistent device scratch --------------------------------------------
__device__ __half  g_h1[2*HB];          // [parity][batch][elem] fp16
__device__ __half  g_h2[2*HB];
__device__ float   g_xT[Ts*Bs];
__device__ unsigned g_garr[8*128];      // per-group arrive counters (512B apart)
__device__ unsigned g_ggen[8*128];      // per-group generation counters

// ---- helpers ---------------------------------------------------------------
__device__ __forceinline__ uint32_t smem_u32(const void* p) {
    uint32_t a;
    asm("{ .reg .u64 t; cvta.to.shared.u64 t, %1; cvt.u32.u64 %0, t; }"
        : "=r"(a) : "l"(p));
    return a;
}
__device__ __forceinline__ float tanh_ap(float x) {
    float y; asm("tanh.approx.f32 %0, %1;" : "=f"(y) : "f"(x)); return y;
}
__device__ __forceinline__ float sig_ap(float x) {
    return fmaf(tanh_ap(0.5f * x), 0.5f, 0.5f);
}
__device__ __forceinline__ void ldsm4(unsigned r[4], uint32_t addr) {
    asm volatile("ldmatrix.sync.aligned.m8n8.x4.shared.b16 {%0,%1,%2,%3}, [%4];"
        : "=r"(r[0]), "=r"(r[1]), "=r"(r[2]), "=r"(r[3]) : "r"(addr));
}
__device__ __forceinline__ void sts128(uint32_t addr, uint4 v) {
    asm volatile("st.shared.v4.b32 [%0], {%1,%2,%3,%4};"
        :: "r"(addr), "r"(v.x), "r"(v.y), "r"(v.z), "r"(v.w) : "memory");
}
__device__ __forceinline__ void mma_fp16(float d[4], const unsigned a[4],
                                         unsigned b0, unsigned b1) {
    asm volatile(
        "mma.sync.aligned.m16n8k16.row.col.f32.f16.f16.f32 "
        "{%0,%1,%2,%3}, {%4,%5,%6,%7}, {%8,%9}, {%0,%1,%2,%3};"
        : "+f"(d[0]), "+f"(d[1]), "+f"(d[2]), "+f"(d[3])
        : "r"(a[0]), "r"(a[1]), "r"(a[2]), "r"(a[3]), "r"(b0), "r"(b1));
}
__device__ __forceinline__ unsigned packh2(float a, float b) {
    return (unsigned)__half_as_ushort(__float2half_rn(a))
         | ((unsigned)__half_as_ushort(__float2half_rn(b)) << 16);
}

// ---- per-group (16 CTA) barrier --------------------------------------------
__device__ __forceinline__ void group_barrier(int grp) {
    __syncthreads();
    if (threadIdx.x == 0) {
        unsigned* arr = &g_garr[grp * 128];
        unsigned* gen = &g_ggen[grp * 128];
        __threadfence();
        unsigned my;
        asm volatile("ld.acquire.gpu.global.u32 %0, [%1];"
                     : "=r"(my) : "l"(gen));
        if (atomicAdd(arr, 1u) == 15u) {
            atomicExch(arr, 0u);
            __threadfence();
            atomicAdd(gen, 1u);
        } else {
            unsigned v;
            do {
                __nanosleep(16);
                asm volatile("ld.acquire.gpu.global.u32 %0, [%1];"
                             : "=r"(v) : "l"(gen));
            } while (v == my);
        }
    }
    __syncthreads();
}

// ---- B staging: chunk = n64 x k128 fp16 = 16KB ------------------------------
__device__ __forceinline__ void ldgB(uint4 pf[4], const __half* __restrict__ h,
                                     int b0, int kc) {
    int n = threadIdx.x >> 2;
    int c0 = (threadIdx.x & 3) * 4;
    const uint4* p = (const uint4*)(h + (size_t)(b0 + n) * Hs + kc * 128 + c0 * 8);
    pf[0] = __ldcg(p);     pf[1] = __ldcg(p + 1);
    pf[2] = __ldcg(p + 2); pf[3] = __ldcg(p + 3);
}
__device__ __forceinline__ void stsB(uint32_t buf, const uint4 pf[4]) {
    int n = threadIdx.x >> 2;
    int c0 = (threadIdx.x & 3) * 4;
    #pragma unroll
    for (int j = 0; j < 4; ++j)
        sts128(buf + n * 256 + (((c0 + j + n) & 15) << 4), pf[j]);
}

// ---- MMA on one staged chunk (KC=128, 8 ksteps) ------------------------------
__device__ __forceinline__ void gemm_chunk(
    uint32_t wBase, uint32_t bBuf, int kcA, float acc[4][4],
    int m_a, uint32_t aRowOff, int kh_a, int n_b, uint32_t bRowOff, int kh_b)
{
    #pragma unroll
    for (int ks = 0; ks < 8; ++ks) {
        unsigned ah[4], b0[4], b1[4];
        int ca = kcA * 16 + ks * 2 + kh_a;
        ldsm4(ah, wBase + aRowOff + (((ca + m_a) & 31) << 4));
        int cb = ks * 2 + kh_b;
        uint32_t bAddr = bBuf + bRowOff + (((cb + n_b) & 15) << 4);
        ldsm4(b0, bAddr);
        ldsm4(b1, bAddr + 4096);          // n +16 rows
        mma_fp16(acc[0], ah, b0[0], b0[1]);
        mma_fp16(acc[1], ah, b0[2], b0[3]);
        mma_fp16(acc[2], ah, b1[0], b1[1]);
        mma_fp16(acc[3], ah, b1[2], b1[3]);
    }
}

// ---- epilogue: one internal sync (Dsm is a dedicated region) -----------------
__device__ __forceinline__ void epilogue(
    float* __restrict__ Dsm, float acc[4][4], int m0, int wn,
    const float* __restrict__ bias_sm, const float* __restrict__ w0_sm,
    float xv, float cst[4], __half* __restrict__ hdst, int b0, int e0)
{
    const int tid = threadIdx.x, l = tid & 31;
    const int qrow = l >> 2, qcol = (l & 3) * 2;
    #pragma unroll
    for (int nt = 0; nt < 4; ++nt) {
        int col = wn * 32 + nt * 8 + qcol;
        *(float2*)&Dsm[(m0 + qrow) * 68 + col]     = make_float2(acc[nt][0], acc[nt][1]);
        *(float2*)&Dsm[(m0 + 8 + qrow) * 68 + col] = make_float2(acc[nt][2], acc[nt][3]);
    }
    __syncthreads();
    const int bl = tid & 63, eq = tid >> 6;
    unsigned pk[2];
    #pragma unroll
    for (int jj = 0; jj < 2; ++jj) {
        float hv2[2];
        #pragma unroll
        for (int j2 = 0; j2 < 2; ++j2) {
            int j = jj * 2 + j2;
            int el = eq * 4 + j;
            float gi = Dsm[(el)      * 68 + bl] + bias_sm[el];
            float gf = Dsm[(16 + el) * 68 + bl] + bias_sm[16 + el];
            float gg = Dsm[(32 + el) * 68 + bl] + bias_sm[32 + el];
            float go = Dsm[(48 + el) * 68 + bl] + bias_sm[48 + el];
            if (w0_sm) {
                gi = fmaf(xv, w0_sm[el], gi);
                gf = fmaf(xv, w0_sm[16 + el], gf);
                gg = fmaf(xv, w0_sm[32 + el], gg);
                go = fmaf(xv, w0_sm[48 + el], go);
            }
            float iv = sig_ap(gi), fv = sig_ap(gf);
            float gv = tanh_ap(gg), ov = sig_ap(go);
            float c = fv * cst[j] + iv * gv;
            cst[j] = c;
            hv2[j2] = ov * tanh_ap(c);
        }
        pk[jj] = packh2(hv2[0], hv2[1]);
    }
    *(uint2*)&hdst[(size_t)(b0 + bl) * Hs + e0 + eq * 4] = make_uint2(pk[0], pk[1]);
}

// ---------------------------------------------------------------------------
__global__ void __launch_bounds__(NT, 1) lstm_main(
    const float* __restrict__ Wih0, const float* __restrict__ Whh0,
    const float* __restrict__ bih0, const float* __restrict__ bhh0,
    const float* __restrict__ Wih1, const float* __restrict__ Whh1,
    const float* __restrict__ bih1, const float* __restrict__ bhh1)
{
    extern __shared__ char smc[];
    const uint32_t smb = smem_u32(smc);
    const int tid = threadIdx.x;
    const int mt  = blockIdx.x & 15;
    const int grp = blockIdx.x >> 4;
    const int e0  = mt * 16;
    const int b0  = grp * 64;

    // ---- load weight slices into smem (fp16 single plane, swizzled) ----
    {
        const float* Wg[3] = {Whh0, Whh1, Wih1};
        int m = tid >> 2;                     // gate-row 0..63
        int g = m >> 4, el = m & 15;
        for (int w = 0; w < 3; ++w) {
            const float* row = Wg[w] + (size_t)(g * Hs + e0 + el) * Hs;
            uint32_t whi = smb + SM_W(w);
            #pragma unroll
            for (int c8 = 0; c8 < 8; ++c8) {
                int c = (tid & 3) * 8 + c8;   // 16B-chunk 0..31
                float4 v0 = *(const float4*)&row[c * 8];
                float4 v1 = *(const float4*)&row[c * 8 + 4];
                uint4 hi = make_uint4(packh2(v0.x, v0.y), packh2(v0.z, v0.w),
                                      packh2(v1.x, v1.y), packh2(v1.z, v1.w));
                sts128(whi + m * 512 + (((c + m) & 31) << 4), hi);
            }
        }
    }
    if (tid < 64) {
        int g = tid >> 4, el = tid & 15;
        int row = g * Hs + e0 + el;
        ((float*)(smc + SM_BIAS1))[tid] = bih0[row] + bhh0[row];
        ((float*)(smc + SM_BIAS2))[tid] = bih1[row] + bhh1[row];
        ((float*)(smc + SM_W0))[tid]    = Wih0[row];
    }
    __syncthreads();

    // lane constants for ldmatrix addressing
    const int wid = tid >> 5, l = tid & 31;
    const int wm = wid & 3, wn = wid >> 2;
    const int m0 = wm * 16;
    const int m_a = m0 + (l & 7) + (((l >> 3) & 1) << 3);
    const uint32_t aRowOff = m_a * 512;
    const int kh_a = l >> 4;
    const int n_b = (l & 7) + (((l >> 4) & 1) << 3);
    const uint32_t bRowOff = (wn * 32 + n_b) * 256;
    const int kh_b = (l >> 3) & 1;

    float* Dsm = (float*)(smc + SM_DSM);
    const float* bias1 = (const float*)(smc + SM_BIAS1);
    const float* bias2 = (const float*)(smc + SM_BIAS2);
    const float* w0sm  = (const float*)(smc + SM_W0);

    float c1[4] = {0.f, 0.f, 0.f, 0.f};
    float c2[4] = {0.f, 0.f, 0.f, 0.f};
    float acc[4][4];
    uint4 pf[4];

    for (int i = 0; i <= Ts; ++i) {
        const __half* h1p = g_h1 + (size_t)(i & 1) * HB;        // h1(t=i-1)
        __half*       h1d = g_h1 + (size_t)((i + 1) & 1) * HB;  // h1(t=i)
        const __half* h2p = g_h2 + (size_t)((i + 1) & 1) * HB;  // h2(t=i-2)
        __half*       h2d = g_h2 + (size_t)(i & 1) * HB;        // h2(t=i-1)

        // chunk schedule (KC=128): ch 0-1 = Whh0 x h1p (L1),
        // ch 2-3 = Whh1 x h2p, ch 4-5 = Wih1 x h1p (L2).
        const int chBeg = (i < Ts) ? 0 : 2;
        const int chEnd = (i >= 1) ? 6 : 2;
        float xv = (i < Ts) ? g_xT[(size_t)i * Bs + b0 + (tid & 63)] : 0.f;

        #pragma unroll
        for (int nt = 0; nt < 4; ++nt)
            #pragma unroll
            for (int r = 0; r < 4; ++r) acc[nt][r] = 0.f;

        ldgB(pf, (chBeg == 2) ? h2p : h1p, b0, chBeg & 1);
        #pragma unroll 1
        for (int ch = chBeg; ch < chEnd; ++ch) {
            uint32_t buf = smb + SM_B + (ch & 1) * 16384;
            stsB(buf, pf);
            __syncthreads();
            if (ch + 1 < chEnd) {
                int nc = ch + 1;
                ldgB(pf, (nc >= 2 && nc < 4) ? h2p : h1p, b0, nc & 1);
            }
            gemm_chunk(smb + SM_W(ch >> 1), buf, ch & 1, acc,
                       m_a, aRowOff, kh_a, n_b, bRowOff, kh_b);
            if (ch == 1) {
                epilogue(Dsm, acc, m0, wn, bias1, w0sm, xv, c1, h1d, b0, e0);
                #pragma unroll
                for (int nt = 0; nt < 4; ++nt)
                    #pragma unroll
                    for (int r = 0; r < 4; ++r) acc[nt][r] = 0.f;
            }
        }
        if (i >= 1)
            epilogue(Dsm, acc, m0, wn, bias2, (const float*)0, 0.f, c2, h2d, b0, e0);

        group_barrier(grp);
    }
}

// ---------------------------------------------------------------------------
__global__ void init_states(const float* __restrict__ x) {
    int i0 = blockIdx.x * blockDim.x + threadIdx.x;
    int stride = gridDim.x * blockDim.x;
    unsigned* z1 = (unsigned*)g_h1;
    unsigned* z2 = (unsigned*)g_h2;
    for (int i = i0; i < HB; i += stride) { z1[i] = 0u; z2[i] = 0u; }
    for (int i = i0; i < 8 * 128; i += stride) { g_garr[i] = 0u; g_ggen[i] = 0u; }
    for (int i = i0; i < Ts * Bs; i += stride) {
        int t = i / Bs, b = i % Bs;
        g_xT[i] = x[(size_t)b * Ts + t];
    }
}

__global__ void fc_kernel(const float* __restrict__ Wfc,
                          const float* __restrict__ bfc,
                          float* __restrict__ out)
{
    int b = blockIdx.x * blockDim.x + threadIdx.x;   // 0..511
    const __half* h = g_h2;   // final h2(t=511) in parity-0 buffer
    float acc = 0.f;
    #pragma unroll 8
    for (int e = 0; e < Hs; ++e)
        acc += __half2float(h[(size_t)b * Hs + e]) * Wfc[e];
    out[b] = acc + bfc[0];
}

// ---------------------------------------------------------------------------
extern "C" void kernel_launch(void* const* d_in, const int* in_sizes, int n_in,
                              void* d_out, int out_size)
{
    const float* x    = (const float*)d_in[0];
    const float* Wih0 = (const float*)d_in[1];
    const float* Whh0 = (const float*)d_in[2];
    const float* bih0 = (const float*)d_in[3];
    const float* bhh0 = (const float*)d_in[4];
    const float* Wih1 = (const float*)d_in[5];
    const float* Whh1 = (const float*)d_in[6];
    const float* bih1 = (const float*)d_in[7];
    const float* bhh1 = (const float*)d_in[8];
    const float* Wfc  = (const float*)d_in[9];
    const float* bfc  = (const float*)d_in[10];
    float* out = (float*)d_out;

    static bool attr_set = false;
    if (!attr_set) {
        cudaFuncSetAttribute(lstm_main,
            cudaFuncAttributeMaxDynamicSharedMemorySize, SMEM_BYTES);
        attr_set = true;
    }

    init_states<<<512, 256>>>(x);
    lstm_main<<<NCTA, NT, SMEM_BYTES>>>(Wih0, Whh0, bih0, bhh0,
                                        Wih1, Whh1, bih1, bhh1);
    fc_kernel<<<Bs / 256, 256>>>(Wfc, bfc, out);
}